// round 1
// baseline (speedup 1.0000x reference)
#include <cuda_runtime.h>

#define B_  2
#define S_  2048
#define D_  2048
#define H_  16
#define DH_ 128
#define M_  (B_ * S_)   // 4096

// ---------------- scratch (device globals; no allocation allowed) ----------
__device__ float g_q[(size_t)M_ * D_];
__device__ float g_k[(size_t)M_ * D_];
__device__ float g_v[(size_t)M_ * D_];
__device__ float g_att[(size_t)M_ * D_];

// ---------------- SGEMM: C[m,n] = sum_k A[m,k] * W[n,k] + bias[n] ----------
// 128x128 block tile, BK=16, 256 threads, 8x8 micro-tile per thread.
__global__ __launch_bounds__(256, 2)
void sgemm_bias(const float* __restrict__ A, const float* __restrict__ W,
                const float* __restrict__ bias, float* __restrict__ C,
                int M, int N, int K)
{
    __shared__ float As[16][128];
    __shared__ float Bs[16][128];

    const int tid  = threadIdx.x;
    const int tx   = tid & 15;       // 0..15
    const int ty   = tid >> 4;       // 0..15
    const int row0 = blockIdx.y << 7;
    const int col0 = blockIdx.x << 7;
    const int lr   = tid & 63;       // tile row base for loads
    const int lc   = tid >> 6;       // float4 column (0..3)

    float acc[8][8];
#pragma unroll
    for (int i = 0; i < 8; i++)
#pragma unroll
        for (int j = 0; j < 8; j++) acc[i][j] = 0.f;

    for (int k0 = 0; k0 < K; k0 += 16) {
#pragma unroll
        for (int i = 0; i < 2; i++) {
            int r = lr + i * 64;
            float4 a4 = *(const float4*)(A + (size_t)(row0 + r) * K + k0 + lc * 4);
            As[lc * 4 + 0][r] = a4.x;
            As[lc * 4 + 1][r] = a4.y;
            As[lc * 4 + 2][r] = a4.z;
            As[lc * 4 + 3][r] = a4.w;
            float4 b4 = *(const float4*)(W + (size_t)(col0 + r) * K + k0 + lc * 4);
            Bs[lc * 4 + 0][r] = b4.x;
            Bs[lc * 4 + 1][r] = b4.y;
            Bs[lc * 4 + 2][r] = b4.z;
            Bs[lc * 4 + 3][r] = b4.w;
        }
        __syncthreads();

#pragma unroll
        for (int kk = 0; kk < 16; kk++) {
            float a[8], b[8];
#pragma unroll
            for (int i = 0; i < 8; i++) a[i] = As[kk][ty * 8 + i];       // broadcast
#pragma unroll
            for (int j = 0; j < 8; j++) b[j] = Bs[kk][tx + j * 16];      // conflict-free
#pragma unroll
            for (int i = 0; i < 8; i++)
#pragma unroll
                for (int j = 0; j < 8; j++)
                    acc[i][j] = fmaf(a[i], b[j], acc[i][j]);
        }
        __syncthreads();
    }

#pragma unroll
    for (int j = 0; j < 8; j++) {
        int c = col0 + tx + j * 16;
        float bv = bias[c];
#pragma unroll
        for (int i = 0; i < 8; i++)
            C[(size_t)(row0 + ty * 8 + i) * N + c] = acc[i][j] + bv;
    }
}

// ---------------- RoPE (in-place on q and k) -------------------------------
// layout [b][s][h*128 + d]; pair (d, d+64), theta = s * 10000^(-d/64)
__global__ void rope_kernel(float* __restrict__ q, float* __restrict__ k)
{
    int idx = blockIdx.x * blockDim.x + threadIdx.x;   // 0 .. 2^22-1
    int d0 = idx & 63;
    int h  = (idx >> 6) & (H_ - 1);
    int s  = (idx >> 10) & (S_ - 1);
    int b  = idx >> 21;

    // inv_freq = 10000^(-d0/64) = 2^(-d0 * log2(10000)/64)
    float inv = exp2f(-(float)d0 * (13.287712379549449f / 64.f));
    float ang = (float)s * inv;
    float sn, cs;
    sincosf(ang, &sn, &cs);

    size_t base = ((size_t)(b * S_ + s) * D_) + (size_t)h * DH_ + d0;

    float q1 = q[base], q2 = q[base + 64];
    q[base]      = q1 * cs - q2 * sn;
    q[base + 64] = q2 * cs + q1 * sn;

    float k1 = k[base], k2 = k[base + 64];
    k[base]      = k1 * cs - k2 * sn;
    k[base + 64] = k2 * cs + k1 * sn;
}

// ---------------- Flash attention (fp32, online softmax) -------------------
// Bq = Bk = 64, Dh = 128, 256 threads. grid = (S/64, B*H).
#define QS_STRIDE 128
#define KS_STRIDE 132   // padded: lanes step by 132 floats -> distinct banks
#define VS_STRIDE 128
#define SS_STRIDE 65
#define FLASH_SMEM_FLOATS (64*QS_STRIDE + 64*KS_STRIDE + 64*VS_STRIDE + 64*SS_STRIDE + 3*64)
#define FLASH_SMEM_BYTES  (FLASH_SMEM_FLOATS * 4)

__global__ __launch_bounds__(256)
void flash_kernel(const float* __restrict__ q, const float* __restrict__ k,
                  const float* __restrict__ v, float* __restrict__ o)
{
    extern __shared__ float sm[];
    float* Qs    = sm;                       // [64][128]
    float* Ks    = Qs + 64 * QS_STRIDE;      // [64][132]
    float* Vs    = Ks + 64 * KS_STRIDE;      // [64][128]
    float* Ss    = Vs + 64 * VS_STRIDE;      // [64][65]
    float* row_m = Ss + 64 * SS_STRIDE;
    float* row_l = row_m + 64;
    float* row_a = row_l + 64;

    const int tid = threadIdx.x;
    const int tx  = tid & 15;   // 0..15
    const int ty  = tid >> 4;   // 0..15
    const int q0  = blockIdx.x * 64;
    const int bh  = blockIdx.y;
    const int b   = bh >> 4, h = bh & 15;
    const size_t head = (size_t)b * S_ * D_ + (size_t)h * DH_;

    // load Q tile (64 x 128)
#pragma unroll
    for (int t = 0; t < 8; t++) {
        int f = tid + t * 256;
        int r = f >> 5, c4 = f & 31;
        *(float4*)(Qs + r * QS_STRIDE + c4 * 4) =
            *(const float4*)(q + head + (size_t)(q0 + r) * D_ + c4 * 4);
    }
    if (tid < 64) { row_m[tid] = -1e30f; row_l[tid] = 0.f; }

    float acc[4][8];
#pragma unroll
    for (int i = 0; i < 4; i++)
#pragma unroll
        for (int j = 0; j < 8; j++) acc[i][j] = 0.f;

    const float scale = 0.08838834764831845f;  // 1/sqrt(128)
    __syncthreads();

    for (int kt = 0; kt < S_ / 64; kt++) {
        const int k0 = kt * 64;
        // load K/V tiles
#pragma unroll
        for (int t = 0; t < 8; t++) {
            int f = tid + t * 256;
            int r = f >> 5, c4 = f & 31;
            *(float4*)(Ks + r * KS_STRIDE + c4 * 4) =
                *(const float4*)(k + head + (size_t)(k0 + r) * D_ + c4 * 4);
            *(float4*)(Vs + r * VS_STRIDE + c4 * 4) =
                *(const float4*)(v + head + (size_t)(k0 + r) * D_ + c4 * 4);
        }
        __syncthreads();

        // S = Q K^T : thread (ty,tx) -> rows ty*4+i, cols tx + j*16
        float sacc[4][4];
#pragma unroll
        for (int i = 0; i < 4; i++)
#pragma unroll
            for (int j = 0; j < 4; j++) sacc[i][j] = 0.f;

        for (int d = 0; d < 128; d += 4) {
            float4 qv[4], kv[4];
#pragma unroll
            for (int i = 0; i < 4; i++)
                qv[i] = *(const float4*)(Qs + (ty * 4 + i) * QS_STRIDE + d);
#pragma unroll
            for (int j = 0; j < 4; j++)
                kv[j] = *(const float4*)(Ks + (tx + j * 16) * KS_STRIDE + d);
#pragma unroll
            for (int i = 0; i < 4; i++)
#pragma unroll
                for (int j = 0; j < 4; j++) {
                    sacc[i][j] = fmaf(qv[i].x, kv[j].x, sacc[i][j]);
                    sacc[i][j] = fmaf(qv[i].y, kv[j].y, sacc[i][j]);
                    sacc[i][j] = fmaf(qv[i].z, kv[j].z, sacc[i][j]);
                    sacc[i][j] = fmaf(qv[i].w, kv[j].w, sacc[i][j]);
                }
        }
#pragma unroll
        for (int i = 0; i < 4; i++)
#pragma unroll
            for (int j = 0; j < 4; j++)
                Ss[(ty * 4 + i) * SS_STRIDE + tx + j * 16] = sacc[i][j] * scale;
        __syncthreads();

        // online softmax: one thread per row
        if (tid < 64) {
            const int r = tid;
            float m_old = row_m[r];
            float m_new = m_old;
#pragma unroll 8
            for (int c = 0; c < 64; c++) m_new = fmaxf(m_new, Ss[r * SS_STRIDE + c]);
            float alpha = __expf(m_old - m_new);
            float sum = 0.f;
#pragma unroll 8
            for (int c = 0; c < 64; c++) {
                float p = __expf(Ss[r * SS_STRIDE + c] - m_new);
                Ss[r * SS_STRIDE + c] = p;
                sum += p;
            }
            row_l[r] = row_l[r] * alpha + sum;
            row_m[r] = m_new;
            row_a[r] = alpha;
        }
        __syncthreads();

        // rescale O and accumulate O += P V
#pragma unroll
        for (int i = 0; i < 4; i++) {
            float a = row_a[ty * 4 + i];
#pragma unroll
            for (int j = 0; j < 8; j++) acc[i][j] *= a;
        }
#pragma unroll 4
        for (int c = 0; c < 64; c++) {
            float p0 = Ss[(ty * 4 + 0) * SS_STRIDE + c];
            float p1 = Ss[(ty * 4 + 1) * SS_STRIDE + c];
            float p2 = Ss[(ty * 4 + 2) * SS_STRIDE + c];
            float p3 = Ss[(ty * 4 + 3) * SS_STRIDE + c];
#pragma unroll
            for (int j = 0; j < 8; j++) {
                float vv = Vs[c * VS_STRIDE + tx + j * 16];
                acc[0][j] = fmaf(p0, vv, acc[0][j]);
                acc[1][j] = fmaf(p1, vv, acc[1][j]);
                acc[2][j] = fmaf(p2, vv, acc[2][j]);
                acc[3][j] = fmaf(p3, vv, acc[3][j]);
            }
        }
        __syncthreads();
    }

    // normalize and write (b, s, h*128 + d) layout -> feeds final projection
#pragma unroll
    for (int i = 0; i < 4; i++) {
        const int r = ty * 4 + i;
        const float inv_l = 1.f / row_l[r];
#pragma unroll
        for (int j = 0; j < 8; j++)
            o[head + (size_t)(q0 + r) * D_ + tx + j * 16] = acc[i][j] * inv_l;
    }
}

// ---------------- launch ---------------------------------------------------
extern "C" void kernel_launch(void* const* d_in, const int* in_sizes, int n_in,
                              void* d_out, int out_size)
{
    const float* x   = (const float*)d_in[0];
    const float* q_w = (const float*)d_in[1];
    const float* k_w = (const float*)d_in[2];
    const float* v_w = (const float*)d_in[3];
    const float* q_b = (const float*)d_in[4];
    const float* k_b = (const float*)d_in[5];
    const float* v_b = (const float*)d_in[6];
    const float* o_w = (const float*)d_in[7];
    const float* o_b = (const float*)d_in[8];
    float* out = (float*)d_out;

    float *qp, *kp, *vp, *ap;
    cudaGetSymbolAddress((void**)&qp, g_q);
    cudaGetSymbolAddress((void**)&kp, g_k);
    cudaGetSymbolAddress((void**)&vp, g_v);
    cudaGetSymbolAddress((void**)&ap, g_att);

    cudaFuncSetAttribute(flash_kernel,
                         cudaFuncAttributeMaxDynamicSharedMemorySize,
                         FLASH_SMEM_BYTES);

    dim3 gg(D_ / 128, M_ / 128);  // (16, 32)
    dim3 bb(256);

    sgemm_bias<<<gg, bb>>>(x, q_w, q_b, qp, M_, D_, D_);
    sgemm_bias<<<gg, bb>>>(x, k_w, k_b, kp, M_, D_, D_);
    sgemm_bias<<<gg, bb>>>(x, v_w, v_b, vp, M_, D_, D_);

    rope_kernel<<<(B_ * S_ * H_ * 64) / 256, 256>>>(qp, kp);

    flash_kernel<<<dim3(S_ / 64, B_ * H_), 256, FLASH_SMEM_BYTES>>>(qp, kp, vp, ap);

    sgemm_bias<<<gg, bb>>>(ap, o_w, o_b, out, M_, D_, D_);
}

// round 5
// speedup vs baseline: 1.8444x; 1.8444x over previous
#include <cuda_runtime.h>
#include <cstdint>

#define B_  2
#define S_  2048
#define D_  2048
#define H_  16
#define DH_ 128
#define M_  (B_ * S_)   // 4096

// ---------------- scratch (device globals; no allocation allowed) ----------
__device__ float g_q[(size_t)M_ * D_];
__device__ float g_k[(size_t)M_ * D_];
__device__ float g_v[(size_t)M_ * D_];
__device__ float g_att[(size_t)M_ * D_];

// =================== tf32 mma.sync GEMM ====================================
// C[m,n] = sum_k A[m,k] * W[n,k] + bias[n]
// CTA tile 128x128, BK=32, 256 threads = 8 warps (2 x 4), warp tile 64x32.
// mma.sync.aligned.m16n8k8.row.col.f32.tf32.tf32.f32
// smem stride 36 floats -> conflict-free fragment loads.

#define GST 36   // smem row stride in floats

__device__ __forceinline__ uint32_t f2tf32(float x) {
    uint32_t r;
    asm("cvt.rna.tf32.f32 %0, %1;" : "=r"(r) : "f"(x));
    return r;
}

__device__ __forceinline__ void mma_tf32(float* d,
                                         const uint32_t* a,
                                         const uint32_t* b) {
    asm volatile(
        "mma.sync.aligned.m16n8k8.row.col.f32.tf32.tf32.f32 "
        "{%0,%1,%2,%3}, {%4,%5,%6,%7}, {%8,%9}, {%0,%1,%2,%3};"
        : "+f"(d[0]), "+f"(d[1]), "+f"(d[2]), "+f"(d[3])
        : "r"(a[0]), "r"(a[1]), "r"(a[2]), "r"(a[3]),
          "r"(b[0]), "r"(b[1]));
}

__global__ __launch_bounds__(256)
void mma_gemm_bias(const float* __restrict__ A, const float* __restrict__ W,
                   const float* __restrict__ bias, float* __restrict__ C,
                   int K)
{
    __shared__ uint32_t sA[128 * GST];
    __shared__ uint32_t sB[128 * GST];

    const int tid  = threadIdx.x;
    const int wid  = tid >> 5;
    const int lane = tid & 31;
    const int wm   = wid >> 2;          // 0..1  (M direction, 64 rows each)
    const int wn   = wid & 3;           // 0..3  (N direction, 32 cols each)
    const int row0 = blockIdx.y << 7;
    const int col0 = blockIdx.x << 7;

    const int lq = lane >> 2;           // 0..7
    const int lr = lane & 3;            // 0..3

    // global load indices: 4 float4 per thread per operand tile (128x32)
    const int gm  = tid >> 1;                  // not used directly; see loop
    (void)gm;

    float4 ra[4], rb[4];

    // accumulators: [mb][nb][4]
    float acc[4][4][4];
#pragma unroll
    for (int i = 0; i < 4; i++)
#pragma unroll
        for (int j = 0; j < 4; j++)
#pragma unroll
            for (int r = 0; r < 4; r++) acc[i][j][r] = 0.f;

    const int NCH = K / 32;

    // ---- prologue: load chunk 0 into registers
#pragma unroll
    for (int i = 0; i < 4; i++) {
        int f  = tid + i * 256;      // 0..1023
        int m  = f >> 3;
        int c4 = f & 7;
        ra[i] = *(const float4*)(A + (size_t)(row0 + m) * K + c4 * 4);
        rb[i] = *(const float4*)(W + (size_t)(col0 + m) * K + c4 * 4);
    }

    for (int ch = 0; ch < NCH; ch++) {
        // ---- store staged registers to smem (with tf32 conversion)
#pragma unroll
        for (int i = 0; i < 4; i++) {
            int f  = tid + i * 256;
            int m  = f >> 3;
            int c4 = f & 7;
            uint32_t* pa = &sA[m * GST + c4 * 4];
            pa[0] = f2tf32(ra[i].x); pa[1] = f2tf32(ra[i].y);
            pa[2] = f2tf32(ra[i].z); pa[3] = f2tf32(ra[i].w);
            uint32_t* pb = &sB[m * GST + c4 * 4];
            pb[0] = f2tf32(rb[i].x); pb[1] = f2tf32(rb[i].y);
            pb[2] = f2tf32(rb[i].z); pb[3] = f2tf32(rb[i].w);
        }
        __syncthreads();

        // ---- prefetch next chunk (overlaps with MMA compute below)
        if (ch + 1 < NCH) {
            const int kb = (ch + 1) * 32;
#pragma unroll
            for (int i = 0; i < 4; i++) {
                int f  = tid + i * 256;
                int m  = f >> 3;
                int c4 = f & 7;
                ra[i] = *(const float4*)(A + (size_t)(row0 + m) * K + kb + c4 * 4);
                rb[i] = *(const float4*)(W + (size_t)(col0 + m) * K + kb + c4 * 4);
            }
        }

        // ---- compute: 4 k-steps of 8
#pragma unroll
        for (int kk = 0; kk < 4; kk++) {
            const int k0 = kk * 8;
            uint32_t afr[4][4], bfr[4][2];
#pragma unroll
            for (int mb = 0; mb < 4; mb++) {
                const int r = wm * 64 + mb * 16 + lq;
                afr[mb][0] = sA[(r    ) * GST + k0 + lr    ];
                afr[mb][1] = sA[(r + 8) * GST + k0 + lr    ];
                afr[mb][2] = sA[(r    ) * GST + k0 + lr + 4];
                afr[mb][3] = sA[(r + 8) * GST + k0 + lr + 4];
            }
#pragma unroll
            for (int nb = 0; nb < 4; nb++) {
                const int n = wn * 32 + nb * 8 + lq;
                bfr[nb][0] = sB[n * GST + k0 + lr    ];
                bfr[nb][1] = sB[n * GST + k0 + lr + 4];
            }
#pragma unroll
            for (int mb = 0; mb < 4; mb++)
#pragma unroll
                for (int nb = 0; nb < 4; nb++)
                    mma_tf32(acc[mb][nb], afr[mb], bfr[nb]);
        }
        __syncthreads();
    }

    // ---- epilogue: bias add + store (float2 per c-pair)
#pragma unroll
    for (int mb = 0; mb < 4; mb++) {
#pragma unroll
        for (int nb = 0; nb < 4; nb++) {
            const int col = col0 + wn * 32 + nb * 8 + lr * 2;
            const float2 bv = *(const float2*)(bias + col);
            const int r0 = row0 + wm * 64 + mb * 16 + lq;
            float2 o0, o1;
            o0.x = acc[mb][nb][0] + bv.x;
            o0.y = acc[mb][nb][1] + bv.y;
            o1.x = acc[mb][nb][2] + bv.x;
            o1.y = acc[mb][nb][3] + bv.y;
            *(float2*)(C + (size_t)r0 * D_ + col)       = o0;
            *(float2*)(C + (size_t)(r0 + 8) * D_ + col) = o1;
        }
    }
}

// ---------------- RoPE (in-place on q and k) -------------------------------
__global__ void rope_kernel(float* __restrict__ q, float* __restrict__ k)
{
    int idx = blockIdx.x * blockDim.x + threadIdx.x;
    int d0 = idx & 63;
    int h  = (idx >> 6) & (H_ - 1);
    int s  = (idx >> 10) & (S_ - 1);
    int b  = idx >> 21;

    float inv = exp2f(-(float)d0 * (13.287712379549449f / 64.f));
    float ang = (float)s * inv;
    float sn, cs;
    sincosf(ang, &sn, &cs);

    size_t base = ((size_t)(b * S_ + s) * D_) + (size_t)h * DH_ + d0;

    float q1 = q[base], q2 = q[base + 64];
    q[base]      = q1 * cs - q2 * sn;
    q[base + 64] = q2 * cs + q1 * sn;

    float k1 = k[base], k2 = k[base + 64];
    k[base]      = k1 * cs - k2 * sn;
    k[base + 64] = k2 * cs + k1 * sn;
}

// ---------------- Flash attention (fp32, online softmax) -------------------
#define QS_STRIDE 128
#define KS_STRIDE 132
#define VS_STRIDE 128
#define SS_STRIDE 65
#define FLASH_SMEM_FLOATS (64*QS_STRIDE + 64*KS_STRIDE + 64*VS_STRIDE + 64*SS_STRIDE + 3*64)
#define FLASH_SMEM_BYTES  (FLASH_SMEM_FLOATS * 4)

__global__ __launch_bounds__(256)
void flash_kernel(const float* __restrict__ q, const float* __restrict__ k,
                  const float* __restrict__ v, float* __restrict__ o)
{
    extern __shared__ float sm[];
    float* Qs    = sm;
    float* Ks    = Qs + 64 * QS_STRIDE;
    float* Vs    = Ks + 64 * KS_STRIDE;
    float* Ss    = Vs + 64 * VS_STRIDE;
    float* row_m = Ss + 64 * SS_STRIDE;
    float* row_l = row_m + 64;
    float* row_a = row_l + 64;

    const int tid = threadIdx.x;
    const int tx  = tid & 15;
    const int ty  = tid >> 4;
    const int q0  = blockIdx.x * 64;
    const int bh  = blockIdx.y;
    const int b   = bh >> 4, h = bh & 15;
    const size_t head = (size_t)b * S_ * D_ + (size_t)h * DH_;

#pragma unroll
    for (int t = 0; t < 8; t++) {
        int f = tid + t * 256;
        int r = f >> 5, c4 = f & 31;
        *(float4*)(Qs + r * QS_STRIDE + c4 * 4) =
            *(const float4*)(q + head + (size_t)(q0 + r) * D_ + c4 * 4);
    }
    if (tid < 64) { row_m[tid] = -1e30f; row_l[tid] = 0.f; }

    float acc[4][8];
#pragma unroll
    for (int i = 0; i < 4; i++)
#pragma unroll
        for (int j = 0; j < 8; j++) acc[i][j] = 0.f;

    const float scale = 0.08838834764831845f;
    __syncthreads();

    for (int kt = 0; kt < S_ / 64; kt++) {
        const int k0 = kt * 64;
#pragma unroll
        for (int t = 0; t < 8; t++) {
            int f = tid + t * 256;
            int r = f >> 5, c4 = f & 31;
            *(float4*)(Ks + r * KS_STRIDE + c4 * 4) =
                *(const float4*)(k + head + (size_t)(k0 + r) * D_ + c4 * 4);
            *(float4*)(Vs + r * VS_STRIDE + c4 * 4) =
                *(const float4*)(v + head + (size_t)(k0 + r) * D_ + c4 * 4);
        }
        __syncthreads();

        float sacc[4][4];
#pragma unroll
        for (int i = 0; i < 4; i++)
#pragma unroll
            for (int j = 0; j < 4; j++) sacc[i][j] = 0.f;

        for (int d = 0; d < 128; d += 4) {
            float4 qv[4], kv[4];
#pragma unroll
            for (int i = 0; i < 4; i++)
                qv[i] = *(const float4*)(Qs + (ty * 4 + i) * QS_STRIDE + d);
#pragma unroll
            for (int j = 0; j < 4; j++)
                kv[j] = *(const float4*)(Ks + (tx + j * 16) * KS_STRIDE + d);
#pragma unroll
            for (int i = 0; i < 4; i++)
#pragma unroll
                for (int j = 0; j < 4; j++) {
                    sacc[i][j] = fmaf(qv[i].x, kv[j].x, sacc[i][j]);
                    sacc[i][j] = fmaf(qv[i].y, kv[j].y, sacc[i][j]);
                    sacc[i][j] = fmaf(qv[i].z, kv[j].z, sacc[i][j]);
                    sacc[i][j] = fmaf(qv[i].w, kv[j].w, sacc[i][j]);
                }
        }
#pragma unroll
        for (int i = 0; i < 4; i++)
#pragma unroll
            for (int j = 0; j < 4; j++)
                Ss[(ty * 4 + i) * SS_STRIDE + tx + j * 16] = sacc[i][j] * scale;
        __syncthreads();

        if (tid < 64) {
            const int r = tid;
            float m_old = row_m[r];
            float m_new = m_old;
#pragma unroll 8
            for (int c = 0; c < 64; c++) m_new = fmaxf(m_new, Ss[r * SS_STRIDE + c]);
            float alpha = __expf(m_old - m_new);
            float sum = 0.f;
#pragma unroll 8
            for (int c = 0; c < 64; c++) {
                float p = __expf(Ss[r * SS_STRIDE + c] - m_new);
                Ss[r * SS_STRIDE + c] = p;
                sum += p;
            }
            row_l[r] = row_l[r] * alpha + sum;
            row_m[r] = m_new;
            row_a[r] = alpha;
        }
        __syncthreads();

#pragma unroll
        for (int i = 0; i < 4; i++) {
            float a = row_a[ty * 4 + i];
#pragma unroll
            for (int j = 0; j < 8; j++) acc[i][j] *= a;
        }
#pragma unroll 4
        for (int c = 0; c < 64; c++) {
            float p0 = Ss[(ty * 4 + 0) * SS_STRIDE + c];
            float p1 = Ss[(ty * 4 + 1) * SS_STRIDE + c];
            float p2 = Ss[(ty * 4 + 2) * SS_STRIDE + c];
            float p3 = Ss[(ty * 4 + 3) * SS_STRIDE + c];
#pragma unroll
            for (int j = 0; j < 8; j++) {
                float vv = Vs[c * VS_STRIDE + tx + j * 16];
                acc[0][j] = fmaf(p0, vv, acc[0][j]);
                acc[1][j] = fmaf(p1, vv, acc[1][j]);
                acc[2][j] = fmaf(p2, vv, acc[2][j]);
                acc[3][j] = fmaf(p3, vv, acc[3][j]);
            }
        }
        __syncthreads();
    }

#pragma unroll
    for (int i = 0; i < 4; i++) {
        const int r = ty * 4 + i;
        const float inv_l = 1.f / row_l[r];
#pragma unroll
        for (int j = 0; j < 8; j++)
            o[head + (size_t)(q0 + r) * D_ + tx + j * 16] = acc[i][j] * inv_l;
    }
}

// ---------------- launch ---------------------------------------------------
extern "C" void kernel_launch(void* const* d_in, const int* in_sizes, int n_in,
                              void* d_out, int out_size)
{
    const float* x   = (const float*)d_in[0];
    const float* q_w = (const float*)d_in[1];
    const float* k_w = (const float*)d_in[2];
    const float* v_w = (const float*)d_in[3];
    const float* q_b = (const float*)d_in[4];
    const float* k_b = (const float*)d_in[5];
    const float* v_b = (const float*)d_in[6];
    const float* o_w = (const float*)d_in[7];
    const float* o_b = (const float*)d_in[8];
    float* out = (float*)d_out;

    float *qp, *kp, *vp, *ap;
    cudaGetSymbolAddress((void**)&qp, g_q);
    cudaGetSymbolAddress((void**)&kp, g_k);
    cudaGetSymbolAddress((void**)&vp, g_v);
    cudaGetSymbolAddress((void**)&ap, g_att);

    cudaFuncSetAttribute(flash_kernel,
                         cudaFuncAttributeMaxDynamicSharedMemorySize,
                         FLASH_SMEM_BYTES);

    dim3 gg(D_ / 128, M_ / 128);  // (16, 32)

    mma_gemm_bias<<<gg, 256>>>(x, q_w, q_b, qp, D_);
    mma_gemm_bias<<<gg, 256>>>(x, k_w, k_b, kp, D_);
    mma_gemm_bias<<<gg, 256>>>(x, v_w, v_b, vp, D_);

    rope_kernel<<<(B_ * S_ * H_ * 64) / 256, 256>>>(qp, kp);

    flash_kernel<<<dim3(S_ / 64, B_ * H_), 256, FLASH_SMEM_BYTES>>>(qp, kp, vp, ap);

    mma_gemm_bias<<<gg, 256>>>(ap, o_w, o_b, out, D_);
}

// round 6
// speedup vs baseline: 3.1454x; 1.7054x over previous
#include <cuda_runtime.h>
#include <cstdint>

#define B_  2
#define S_  2048
#define D_  2048
#define H_  16
#define DH_ 128
#define M_  (B_ * S_)   // 4096

// ---------------- scratch (device globals; no allocation allowed) ----------
__device__ float g_q[(size_t)M_ * D_];
__device__ float g_k[(size_t)M_ * D_];
__device__ float g_v[(size_t)M_ * D_];   // V stored TRANSPOSED: [(b*16+h)][d(128)][s(2048)]
__device__ float g_att[(size_t)M_ * D_];

// =================== tf32 mma.sync helpers =================================
__device__ __forceinline__ uint32_t f2tf32(float x) {
    uint32_t r;
    asm("cvt.rna.tf32.f32 %0, %1;" : "=r"(r) : "f"(x));
    return r;
}

__device__ __forceinline__ void mma_tf32(float* d,
                                         const uint32_t* a,
                                         const uint32_t* b) {
    asm volatile(
        "mma.sync.aligned.m16n8k8.row.col.f32.tf32.tf32.f32 "
        "{%0,%1,%2,%3}, {%4,%5,%6,%7}, {%8,%9}, {%0,%1,%2,%3};"
        : "+f"(d[0]), "+f"(d[1]), "+f"(d[2]), "+f"(d[3])
        : "r"(a[0]), "r"(a[1]), "r"(a[2]), "r"(a[3]),
          "r"(b[0]), "r"(b[1]));
}

// =================== tf32 GEMM =============================================
// C[m,n] = sum_k A[m,k] * W[n,k] + bias[n]
// CTA tile 128x128, BK=32, 256 threads = 8 warps (2 x 4), warp tile 64x32.
// VTRANS=1: write output transposed into [(b*16+h)][d][s] layout (for V).
#define GST 36   // smem row stride in floats

template <int VTRANS>
__global__ __launch_bounds__(256)
void mma_gemm_bias(const float* __restrict__ A, const float* __restrict__ W,
                   const float* __restrict__ bias, float* __restrict__ C,
                   int K)
{
    __shared__ uint32_t sA[128 * GST];
    __shared__ uint32_t sB[128 * GST];

    const int tid  = threadIdx.x;
    const int wid  = tid >> 5;
    const int lane = tid & 31;
    const int wm   = wid >> 2;          // 0..1
    const int wn   = wid & 3;           // 0..3
    const int row0 = blockIdx.y << 7;
    const int col0 = blockIdx.x << 7;

    const int lq = lane >> 2;           // 0..7
    const int lr = lane & 3;            // 0..3

    float4 ra[4], rb[4];

    float acc[4][4][4];
#pragma unroll
    for (int i = 0; i < 4; i++)
#pragma unroll
        for (int j = 0; j < 4; j++)
#pragma unroll
            for (int r = 0; r < 4; r++) acc[i][j][r] = 0.f;

    const int NCH = K / 32;

#pragma unroll
    for (int i = 0; i < 4; i++) {
        int f  = tid + i * 256;
        int m  = f >> 3;
        int c4 = f & 7;
        ra[i] = *(const float4*)(A + (size_t)(row0 + m) * K + c4 * 4);
        rb[i] = *(const float4*)(W + (size_t)(col0 + m) * K + c4 * 4);
    }

    for (int ch = 0; ch < NCH; ch++) {
#pragma unroll
        for (int i = 0; i < 4; i++) {
            int f  = tid + i * 256;
            int m  = f >> 3;
            int c4 = f & 7;
            uint32_t* pa = &sA[m * GST + c4 * 4];
            pa[0] = f2tf32(ra[i].x); pa[1] = f2tf32(ra[i].y);
            pa[2] = f2tf32(ra[i].z); pa[3] = f2tf32(ra[i].w);
            uint32_t* pb = &sB[m * GST + c4 * 4];
            pb[0] = f2tf32(rb[i].x); pb[1] = f2tf32(rb[i].y);
            pb[2] = f2tf32(rb[i].z); pb[3] = f2tf32(rb[i].w);
        }
        __syncthreads();

        if (ch + 1 < NCH) {
            const int kb = (ch + 1) * 32;
#pragma unroll
            for (int i = 0; i < 4; i++) {
                int f  = tid + i * 256;
                int m  = f >> 3;
                int c4 = f & 7;
                ra[i] = *(const float4*)(A + (size_t)(row0 + m) * K + kb + c4 * 4);
                rb[i] = *(const float4*)(W + (size_t)(col0 + m) * K + kb + c4 * 4);
            }
        }

#pragma unroll
        for (int kk = 0; kk < 4; kk++) {
            const int k0 = kk * 8;
            uint32_t afr[4][4], bfr[4][2];
#pragma unroll
            for (int mb = 0; mb < 4; mb++) {
                const int r = wm * 64 + mb * 16 + lq;
                afr[mb][0] = sA[(r    ) * GST + k0 + lr    ];
                afr[mb][1] = sA[(r + 8) * GST + k0 + lr    ];
                afr[mb][2] = sA[(r    ) * GST + k0 + lr + 4];
                afr[mb][3] = sA[(r + 8) * GST + k0 + lr + 4];
            }
#pragma unroll
            for (int nb = 0; nb < 4; nb++) {
                const int n = wn * 32 + nb * 8 + lq;
                bfr[nb][0] = sB[n * GST + k0 + lr    ];
                bfr[nb][1] = sB[n * GST + k0 + lr + 4];
            }
#pragma unroll
            for (int mb = 0; mb < 4; mb++)
#pragma unroll
                for (int nb = 0; nb < 4; nb++)
                    mma_tf32(acc[mb][nb], afr[mb], bfr[nb]);
        }
        __syncthreads();
    }

    if (VTRANS) {
        // transposed epilogue: out[(b*16+h)][d][s], h = blockIdx.x
        const int bidx = row0 >> 11;
        const size_t vbase = ((size_t)bidx * 16 + blockIdx.x) * ((size_t)DH_ * S_);
#pragma unroll
        for (int mb = 0; mb < 4; mb++) {
#pragma unroll
            for (int nb = 0; nb < 4; nb++) {
                const int col = wn * 32 + nb * 8 + lr * 2;  // d in 0..127
                const float2 bv = *(const float2*)(bias + col0 + col);
                const int r0 = row0 + wm * 64 + mb * 16 + lq;
                const int s0 = r0 & (S_ - 1);
                C[vbase + (size_t)(col    ) * S_ + s0]     = acc[mb][nb][0] + bv.x;
                C[vbase + (size_t)(col + 1) * S_ + s0]     = acc[mb][nb][1] + bv.y;
                C[vbase + (size_t)(col    ) * S_ + s0 + 8] = acc[mb][nb][2] + bv.x;
                C[vbase + (size_t)(col + 1) * S_ + s0 + 8] = acc[mb][nb][3] + bv.y;
            }
        }
    } else {
#pragma unroll
        for (int mb = 0; mb < 4; mb++) {
#pragma unroll
            for (int nb = 0; nb < 4; nb++) {
                const int col = col0 + wn * 32 + nb * 8 + lr * 2;
                const float2 bv = *(const float2*)(bias + col);
                const int r0 = row0 + wm * 64 + mb * 16 + lq;
                float2 o0, o1;
                o0.x = acc[mb][nb][0] + bv.x;
                o0.y = acc[mb][nb][1] + bv.y;
                o1.x = acc[mb][nb][2] + bv.x;
                o1.y = acc[mb][nb][3] + bv.y;
                *(float2*)(C + (size_t)r0 * D_ + col)       = o0;
                *(float2*)(C + (size_t)(r0 + 8) * D_ + col) = o1;
            }
        }
    }
}

// ---------------- RoPE (in-place on q and k) -------------------------------
__global__ void rope_kernel(float* __restrict__ q, float* __restrict__ k)
{
    int idx = blockIdx.x * blockDim.x + threadIdx.x;
    int d0 = idx & 63;
    int h  = (idx >> 6) & (H_ - 1);
    int s  = (idx >> 10) & (S_ - 1);
    int b  = idx >> 21;

    float inv = exp2f(-(float)d0 * (13.287712379549449f / 64.f));
    float ang = (float)s * inv;
    float sn, cs;
    sincosf(ang, &sn, &cs);

    size_t base = ((size_t)(b * S_ + s) * D_) + (size_t)h * DH_ + d0;

    float q1 = q[base], q2 = q[base + 64];
    q[base]      = q1 * cs - q2 * sn;
    q[base + 64] = q2 * cs + q1 * sn;

    float k1 = k[base], k2 = k[base + 64];
    k[base]      = k1 * cs - k2 * sn;
    k[base + 64] = k2 * cs + k1 * sn;
}

// ---------------- Flash attention (tf32 tensor-core) -----------------------
// Bq = Bk = 64, Dh = 128, 256 threads = 8 warps: (wm 0..3) x (wn 0..1).
// QK^T: warp tile 16x32.  PV: warp tile 16x64.  V pre-transposed in gmem.
#define FQ_ST 132
#define FK_ST 132
#define FV_ST 68
#define FS_ST 68
#define FLASH_FLOATS (64*FQ_ST + 64*FK_ST + 128*FV_ST + 64*FS_ST + 3*64)
#define FLASH_BYTES  (FLASH_FLOATS * 4)

__global__ __launch_bounds__(256)
void flash_tc(const float* __restrict__ q, const float* __restrict__ k,
              const float* __restrict__ vt, float* __restrict__ o)
{
    extern __shared__ float sm[];
    float* Qs    = sm;                      // [64][132] tf32 bits
    float* Ks    = Qs + 64 * FQ_ST;         // [64][132] tf32 bits
    float* Vs    = Ks + 64 * FK_ST;         // [128 d][68] tf32 bits (transposed V)
    float* Ss    = Vs + 128 * FV_ST;        // [64][68] fp32 scores/probs
    float* row_m = Ss + 64 * FS_ST;
    float* row_l = row_m + 64;
    float* row_a = row_l + 64;

    const int tid  = threadIdx.x;
    const int wid  = tid >> 5;
    const int lane = tid & 31;
    const int lq   = lane >> 2;
    const int lr   = lane & 3;
    const int wm   = wid & 3;     // 0..3
    const int wn   = wid >> 2;    // 0..1
    const int q0   = blockIdx.x * 64;
    const int bh   = blockIdx.y;
    const int b    = bh >> 4, h = bh & 15;
    const size_t head  = (size_t)b * S_ * D_ + (size_t)h * DH_;
    const size_t vhead = (size_t)bh * ((size_t)DH_ * S_);

    // ---- load Q tile, convert tf32, store
#pragma unroll
    for (int t = 0; t < 8; t++) {
        int f = tid + t * 256;
        int r = f >> 5, c4 = f & 31;
        float4 v4 = *(const float4*)(q + head + (size_t)(q0 + r) * D_ + c4 * 4);
        uint4 u;
        u.x = f2tf32(v4.x); u.y = f2tf32(v4.y);
        u.z = f2tf32(v4.z); u.w = f2tf32(v4.w);
        *(uint4*)(Qs + r * FQ_ST + c4 * 4) = u;
    }
    if (tid < 64) { row_m[tid] = -1e30f; row_l[tid] = 0.f; }

    // ---- prologue: stage K/V tile 0 in registers
    float4 rk[8], rv[8];
#pragma unroll
    for (int t = 0; t < 8; t++) {
        int f = tid + t * 256;
        int r = f >> 5, c4 = f & 31;
        rk[t] = *(const float4*)(k + head + (size_t)r * D_ + c4 * 4);
        int rr = f >> 4, cc = f & 15;
        rv[t] = *(const float4*)(vt + vhead + (size_t)rr * S_ + cc * 4);
    }

    float oacc[8][4];
#pragma unroll
    for (int i = 0; i < 8; i++)
#pragma unroll
        for (int j = 0; j < 4; j++) oacc[i][j] = 0.f;

    const float scale = 0.08838834764831845f;  // 1/sqrt(128)
    __syncthreads();

    for (int kt = 0; kt < S_ / 64; kt++) {
        // ---- store staged K/V (tf32) to smem
#pragma unroll
        for (int t = 0; t < 8; t++) {
            int f = tid + t * 256;
            int r = f >> 5, c4 = f & 31;
            uint4 u;
            u.x = f2tf32(rk[t].x); u.y = f2tf32(rk[t].y);
            u.z = f2tf32(rk[t].z); u.w = f2tf32(rk[t].w);
            *(uint4*)(Ks + r * FK_ST + c4 * 4) = u;
            int rr = f >> 4, cc = f & 15;
            uint4 v;
            v.x = f2tf32(rv[t].x); v.y = f2tf32(rv[t].y);
            v.z = f2tf32(rv[t].z); v.w = f2tf32(rv[t].w);
            *(uint4*)(Vs + rr * FV_ST + cc * 4) = v;
        }
        __syncthreads();

        // ---- prefetch next K/V tile
        if (kt + 1 < S_ / 64) {
            const int kg = (kt + 1) * 64;
#pragma unroll
            for (int t = 0; t < 8; t++) {
                int f = tid + t * 256;
                int r = f >> 5, c4 = f & 31;
                rk[t] = *(const float4*)(k + head + (size_t)(kg + r) * D_ + c4 * 4);
                int rr = f >> 4, cc = f & 15;
                rv[t] = *(const float4*)(vt + vhead + (size_t)rr * S_ + kg + cc * 4);
            }
        }

        // ---- S = Q K^T (warp tile 16x32)
        float sacc[4][4];
#pragma unroll
        for (int i = 0; i < 4; i++)
#pragma unroll
            for (int j = 0; j < 4; j++) sacc[i][j] = 0.f;

#pragma unroll
        for (int ks = 0; ks < 16; ks++) {
            const int k0 = ks * 8;
            uint32_t a[4], bq[4][2];
            const int ar = wm * 16 + lq;
            a[0] = __float_as_uint(Qs[(ar    ) * FQ_ST + k0 + lr    ]);
            a[1] = __float_as_uint(Qs[(ar + 8) * FQ_ST + k0 + lr    ]);
            a[2] = __float_as_uint(Qs[(ar    ) * FQ_ST + k0 + lr + 4]);
            a[3] = __float_as_uint(Qs[(ar + 8) * FQ_ST + k0 + lr + 4]);
#pragma unroll
            for (int nb = 0; nb < 4; nb++) {
                const int n = wn * 32 + nb * 8 + lq;
                bq[nb][0] = __float_as_uint(Ks[n * FK_ST + k0 + lr    ]);
                bq[nb][1] = __float_as_uint(Ks[n * FK_ST + k0 + lr + 4]);
            }
#pragma unroll
            for (int nb = 0; nb < 4; nb++) mma_tf32(sacc[nb], a, bq[nb]);
        }

        // ---- write scaled scores
#pragma unroll
        for (int nb = 0; nb < 4; nb++) {
            const int col = wn * 32 + nb * 8 + 2 * lr;
            const int r   = wm * 16 + lq;
            *(float2*)(Ss + (r    ) * FS_ST + col) =
                make_float2(sacc[nb][0] * scale, sacc[nb][1] * scale);
            *(float2*)(Ss + (r + 8) * FS_ST + col) =
                make_float2(sacc[nb][2] * scale, sacc[nb][3] * scale);
        }
        __syncthreads();

        // ---- online softmax (one thread per row)
        if (tid < 64) {
            const int r = tid;
            float m_old = row_m[r];
            float m_new = m_old;
#pragma unroll 8
            for (int c = 0; c < 64; c++) m_new = fmaxf(m_new, Ss[r * FS_ST + c]);
            float alpha = __expf(m_old - m_new);
            float sum = 0.f;
#pragma unroll 8
            for (int c = 0; c < 64; c++) {
                float p = __expf(Ss[r * FS_ST + c] - m_new);
                Ss[r * FS_ST + c] = p;
                sum += p;
            }
            row_l[r] = row_l[r] * alpha + sum;
            row_m[r] = m_new;
            row_a[r] = alpha;
        }
        __syncthreads();

        // ---- rescale O, then O += P V (warp tile 16x64)
        {
            const float al0 = row_a[wm * 16 + lq];
            const float al1 = row_a[wm * 16 + lq + 8];
#pragma unroll
            for (int nb = 0; nb < 8; nb++) {
                oacc[nb][0] *= al0; oacc[nb][1] *= al0;
                oacc[nb][2] *= al1; oacc[nb][3] *= al1;
            }
        }
#pragma unroll
        for (int ks = 0; ks < 8; ks++) {
            const int k0 = ks * 8;
            uint32_t a[4], bv[8][2];
            const int ar = wm * 16 + lq;
            a[0] = f2tf32(Ss[(ar    ) * FS_ST + k0 + lr    ]);
            a[1] = f2tf32(Ss[(ar + 8) * FS_ST + k0 + lr    ]);
            a[2] = f2tf32(Ss[(ar    ) * FS_ST + k0 + lr + 4]);
            a[3] = f2tf32(Ss[(ar + 8) * FS_ST + k0 + lr + 4]);
#pragma unroll
            for (int nb = 0; nb < 8; nb++) {
                const int n = wn * 64 + nb * 8 + lq;
                bv[nb][0] = __float_as_uint(Vs[n * FV_ST + k0 + lr    ]);
                bv[nb][1] = __float_as_uint(Vs[n * FV_ST + k0 + lr + 4]);
            }
#pragma unroll
            for (int nb = 0; nb < 8; nb++) mma_tf32(oacc[nb], a, bv[nb]);
        }
        __syncthreads();
    }

    // ---- epilogue: normalize, write O
    const float il0 = 1.f / row_l[wm * 16 + lq];
    const float il1 = 1.f / row_l[wm * 16 + lq + 8];
#pragma unroll
    for (int nb = 0; nb < 8; nb++) {
        const int col = wn * 64 + nb * 8 + 2 * lr;
        const int r   = q0 + wm * 16 + lq;
        *(float2*)(o + head + (size_t)r * D_ + col) =
            make_float2(oacc[nb][0] * il0, oacc[nb][1] * il0);
        *(float2*)(o + head + (size_t)(r + 8) * D_ + col) =
            make_float2(oacc[nb][2] * il1, oacc[nb][3] * il1);
    }
}

// ---------------- launch ---------------------------------------------------
extern "C" void kernel_launch(void* const* d_in, const int* in_sizes, int n_in,
                              void* d_out, int out_size)
{
    const float* x   = (const float*)d_in[0];
    const float* q_w = (const float*)d_in[1];
    const float* k_w = (const float*)d_in[2];
    const float* v_w = (const float*)d_in[3];
    const float* q_b = (const float*)d_in[4];
    const float* k_b = (const float*)d_in[5];
    const float* v_b = (const float*)d_in[6];
    const float* o_w = (const float*)d_in[7];
    const float* o_b = (const float*)d_in[8];
    float* out = (float*)d_out;

    float *qp, *kp, *vp, *ap;
    cudaGetSymbolAddress((void**)&qp, g_q);
    cudaGetSymbolAddress((void**)&kp, g_k);
    cudaGetSymbolAddress((void**)&vp, g_v);
    cudaGetSymbolAddress((void**)&ap, g_att);

    cudaFuncSetAttribute(flash_tc,
                         cudaFuncAttributeMaxDynamicSharedMemorySize,
                         FLASH_BYTES);

    dim3 gg(D_ / 128, M_ / 128);  // (16, 32)

    mma_gemm_bias<0><<<gg, 256>>>(x, q_w, q_b, qp, D_);
    mma_gemm_bias<0><<<gg, 256>>>(x, k_w, k_b, kp, D_);
    mma_gemm_bias<1><<<gg, 256>>>(x, v_w, v_b, vp, D_);   // V written transposed

    rope_kernel<<<(B_ * S_ * H_ * 64) / 256, 256>>>(qp, kp);

    flash_tc<<<dim3(S_ / 64, B_ * H_), 256, FLASH_BYTES>>>(qp, kp, vp, ap);

    mma_gemm_bias<0><<<gg, 256>>>(ap, o_w, o_b, out, D_);
}

// round 7
// speedup vs baseline: 3.8937x; 1.2379x over previous
#include <cuda_runtime.h>
#include <cstdint>

#define B_  2
#define S_  2048
#define D_  2048
#define H_  16
#define DH_ 128
#define M_  (B_ * S_)   // 4096

// ---------------- scratch (device globals; no allocation allowed) ----------
__device__ float g_q[(size_t)M_ * D_];
__device__ float g_k[(size_t)M_ * D_];
__device__ float g_v[(size_t)M_ * D_];   // V TRANSPOSED: [(b*16+h)][d(128)][s(2048)]
__device__ float g_att[(size_t)M_ * D_]; // written tf32-rounded by flash
__device__ float g_xr[(size_t)M_ * D_];  // tf32-rounded x
__device__ float g_wq[(size_t)D_ * D_];  // tf32-rounded weights
__device__ float g_wk[(size_t)D_ * D_];
__device__ float g_wv[(size_t)D_ * D_];
__device__ float g_wo[(size_t)D_ * D_];

// =================== helpers ===============================================
__device__ __forceinline__ uint32_t f2tf32(float x) {
    uint32_t r;
    asm("cvt.rna.tf32.f32 %0, %1;" : "=r"(r) : "f"(x));
    return r;
}

__device__ __forceinline__ void mma_tf32(float* d,
                                         const uint32_t* a,
                                         const uint32_t* b) {
    asm volatile(
        "mma.sync.aligned.m16n8k8.row.col.f32.tf32.tf32.f32 "
        "{%0,%1,%2,%3}, {%4,%5,%6,%7}, {%8,%9}, {%0,%1,%2,%3};"
        : "+f"(d[0]), "+f"(d[1]), "+f"(d[2]), "+f"(d[3])
        : "r"(a[0]), "r"(a[1]), "r"(a[2]), "r"(a[3]),
          "r"(b[0]), "r"(b[1]));
}

__device__ __forceinline__ void cp16(uint32_t dst, const void* src) {
    asm volatile("cp.async.cg.shared.global [%0], [%1], 16;" :: "r"(dst), "l"(src));
}
#define CP_COMMIT() asm volatile("cp.async.commit_group;" ::: "memory")
#define CP_WAIT(n)  asm volatile("cp.async.wait_group %0;" :: "n"(n) : "memory")

__device__ __forceinline__ uint32_t smem_u32(const void* p) {
    uint32_t a;
    asm("{ .reg .u64 t; cvta.to.shared.u64 t, %1; cvt.u32.u64 %0, t; }"
        : "=r"(a) : "l"(p));
    return a;
}

// ---------------- tf32 pre-round (elementwise) -----------------------------
__global__ void tf32_round_kernel(const float4* __restrict__ in,
                                  float4* __restrict__ out, int n4)
{
    int i = blockIdx.x * blockDim.x + threadIdx.x;
    if (i >= n4) return;
    float4 v = in[i];
    v.x = __uint_as_float(f2tf32(v.x));
    v.y = __uint_as_float(f2tf32(v.y));
    v.z = __uint_as_float(f2tf32(v.z));
    v.w = __uint_as_float(f2tf32(v.w));
    out[i] = v;
}

// =================== cp.async 3-stage tf32 GEMM ============================
// C[m,n] = sum_k A[m,k]*W[n,k] + bias[n].  Inputs pre-rounded to tf32.
// CTA 128x128, BK=32, 256 thr = 8 warps (2x4), warp tile 64x32, 3 smem stages.
// Stage layout: A[128][32] then B[128][32], XOR-swizzled 16B units, stride 128B.
#define STG_BY   32768
#define GEMM_SMEM (3 * STG_BY)

__device__ __forceinline__ void issue_chunk(uint32_t sdst, const float* __restrict__ A,
                                            const float* __restrict__ W,
                                            int row0, int col0, int kb, int tid)
{
#pragma unroll
    for (int i = 0; i < 4; i++) {
        int f = tid + i * 256;
        int row = f >> 3, c4 = f & 7;
        uint32_t doff = (uint32_t)(row * 128 + ((c4 ^ (row & 7)) * 16));
        cp16(sdst + doff,         A + (size_t)(row0 + row) * D_ + kb + c4 * 4);
        cp16(sdst + 16384 + doff, W + (size_t)(col0 + row) * D_ + kb + c4 * 4);
    }
    CP_COMMIT();
}

__device__ __forceinline__ void compute_chunk(const char* __restrict__ sbase,
                                              int wm, int wn, int lq, int lr,
                                              float acc[4][4][4])
{
    const char* Ab = sbase;
    const char* Bb = sbase + 16384;
#pragma unroll
    for (int kk = 0; kk < 4; kk++) {
        const int sw0 = ((2 * kk)     ^ lq) * 16;
        const int sw1 = ((2 * kk + 1) ^ lq) * 16;
        uint32_t afr[4][4], bfr[4][2];
#pragma unroll
        for (int mb = 0; mb < 4; mb++) {
            const char* p = Ab + (wm * 64 + mb * 16 + lq) * 128 + lr * 4;
            afr[mb][0] = *(const uint32_t*)(p + sw0);
            afr[mb][1] = *(const uint32_t*)(p + 8 * 128 + sw0);
            afr[mb][2] = *(const uint32_t*)(p + sw1);
            afr[mb][3] = *(const uint32_t*)(p + 8 * 128 + sw1);
        }
#pragma unroll
        for (int nb = 0; nb < 4; nb++) {
            const char* p = Bb + (wn * 32 + nb * 8 + lq) * 128 + lr * 4;
            bfr[nb][0] = *(const uint32_t*)(p + sw0);
            bfr[nb][1] = *(const uint32_t*)(p + sw1);
        }
#pragma unroll
        for (int mb = 0; mb < 4; mb++)
#pragma unroll
            for (int nb = 0; nb < 4; nb++)
                mma_tf32(acc[mb][nb], afr[mb], bfr[nb]);
    }
}

// FUSED=1: grid.z in {0,1,2} selects (W,bias,C); z==2 writes V transposed.
template <int FUSED>
__global__ __launch_bounds__(256, 2)
void gemm_tc(const float* __restrict__ A,
             const float* __restrict__ W0, const float* __restrict__ W1,
             const float* __restrict__ W2,
             const float* __restrict__ b0, const float* __restrict__ b1,
             const float* __restrict__ b2,
             float* __restrict__ C0, float* __restrict__ C1,
             float* __restrict__ C2)
{
    extern __shared__ char dsm[];
    const uint32_t s_u32 = smem_u32(dsm);

    const int z = FUSED ? blockIdx.z : 0;
    const float* W    = (z == 0) ? W0 : (z == 1) ? W1 : W2;
    const float* bias = (z == 0) ? b0 : (z == 1) ? b1 : b2;
    float*       C    = (z == 0) ? C0 : (z == 1) ? C1 : C2;

    const int tid  = threadIdx.x;
    const int wid  = tid >> 5;
    const int lane = tid & 31;
    const int wm   = wid >> 2;
    const int wn   = wid & 3;
    const int lq   = lane >> 2;
    const int lr   = lane & 3;
    const int row0 = blockIdx.y << 7;
    const int col0 = blockIdx.x << 7;

    float acc[4][4][4];
#pragma unroll
    for (int i = 0; i < 4; i++)
#pragma unroll
        for (int j = 0; j < 4; j++)
#pragma unroll
            for (int r = 0; r < 4; r++) acc[i][j][r] = 0.f;

    const int NCH = D_ / 32;   // 64

    issue_chunk(s_u32,          A, W, row0, col0, 0,  tid);
    issue_chunk(s_u32 + STG_BY, A, W, row0, col0, 32, tid);

    for (int ch = 0; ch < NCH - 2; ch++) {
        issue_chunk(s_u32 + ((ch + 2) % 3) * STG_BY, A, W, row0, col0,
                    (ch + 2) * 32, tid);
        CP_WAIT(2);
        __syncthreads();
        compute_chunk(dsm + (ch % 3) * STG_BY, wm, wn, lq, lr, acc);
        __syncthreads();
    }
    CP_WAIT(1);
    __syncthreads();
    compute_chunk(dsm + ((NCH - 2) % 3) * STG_BY, wm, wn, lq, lr, acc);
    __syncthreads();
    CP_WAIT(0);
    __syncthreads();
    compute_chunk(dsm + ((NCH - 1) % 3) * STG_BY, wm, wn, lq, lr, acc);

    if (FUSED && z == 2) {
        // V transposed epilogue: out[(b*16+h)][d][s], h = blockIdx.x
        const int bidx = row0 >> 11;
        const size_t vbase = ((size_t)bidx * 16 + blockIdx.x) * ((size_t)DH_ * S_);
#pragma unroll
        for (int mb = 0; mb < 4; mb++) {
#pragma unroll
            for (int nb = 0; nb < 4; nb++) {
                const int col = wn * 32 + nb * 8 + lr * 2;
                const float2 bv = *(const float2*)(bias + col0 + col);
                const int r0 = row0 + wm * 64 + mb * 16 + lq;
                const int s0 = r0 & (S_ - 1);
                C[vbase + (size_t)(col    ) * S_ + s0]     = acc[mb][nb][0] + bv.x;
                C[vbase + (size_t)(col + 1) * S_ + s0]     = acc[mb][nb][1] + bv.y;
                C[vbase + (size_t)(col    ) * S_ + s0 + 8] = acc[mb][nb][2] + bv.x;
                C[vbase + (size_t)(col + 1) * S_ + s0 + 8] = acc[mb][nb][3] + bv.y;
            }
        }
    } else {
#pragma unroll
        for (int mb = 0; mb < 4; mb++) {
#pragma unroll
            for (int nb = 0; nb < 4; nb++) {
                const int col = col0 + wn * 32 + nb * 8 + lr * 2;
                const float2 bv = *(const float2*)(bias + col);
                const int r0 = row0 + wm * 64 + mb * 16 + lq;
                float2 o0, o1;
                o0.x = acc[mb][nb][0] + bv.x;
                o0.y = acc[mb][nb][1] + bv.y;
                o1.x = acc[mb][nb][2] + bv.x;
                o1.y = acc[mb][nb][3] + bv.y;
                *(float2*)(C + (size_t)r0 * D_ + col)       = o0;
                *(float2*)(C + (size_t)(r0 + 8) * D_ + col) = o1;
            }
        }
    }
}

// ---------------- RoPE (in-place on q and k) -------------------------------
__global__ void rope_kernel(float* __restrict__ q, float* __restrict__ k)
{
    int idx = blockIdx.x * blockDim.x + threadIdx.x;
    int d0 = idx & 63;
    int h  = (idx >> 6) & (H_ - 1);
    int s  = (idx >> 10) & (S_ - 1);
    int b  = idx >> 21;

    float inv = exp2f(-(float)d0 * (13.287712379549449f / 64.f));
    float ang = (float)s * inv;
    float sn, cs;
    sincosf(ang, &sn, &cs);

    size_t base = ((size_t)(b * S_ + s) * D_) + (size_t)h * DH_ + d0;

    float q1 = q[base], q2 = q[base + 64];
    q[base]      = q1 * cs - q2 * sn;
    q[base + 64] = q2 * cs + q1 * sn;

    float k1 = k[base], k2 = k[base + 64];
    k[base]      = k1 * cs - k2 * sn;
    k[base + 64] = k2 * cs + k1 * sn;
}

// ---------------- Flash attention (tf32 tensor-core) -----------------------
#define FQ_ST 132
#define FK_ST 132
#define FV_ST 68
#define FS_ST 68
#define FLASH_FLOATS (64*FQ_ST + 64*FK_ST + 128*FV_ST + 64*FS_ST + 3*64)
#define FLASH_BYTES  (FLASH_FLOATS * 4)

__global__ __launch_bounds__(256)
void flash_tc(const float* __restrict__ q, const float* __restrict__ k,
              const float* __restrict__ vt, float* __restrict__ o)
{
    extern __shared__ float sm[];
    float* Qs    = sm;
    float* Ks    = Qs + 64 * FQ_ST;
    float* Vs    = Ks + 64 * FK_ST;
    float* Ss    = Vs + 128 * FV_ST;
    float* row_m = Ss + 64 * FS_ST;
    float* row_l = row_m + 64;
    float* row_a = row_l + 64;

    const int tid  = threadIdx.x;
    const int wid  = tid >> 5;
    const int lane = tid & 31;
    const int lq   = lane >> 2;
    const int lr   = lane & 3;
    const int wm   = wid & 3;
    const int wn   = wid >> 2;
    const int q0   = blockIdx.x * 64;
    const int bh   = blockIdx.y;
    const int b    = bh >> 4, h = bh & 15;
    const size_t head  = (size_t)b * S_ * D_ + (size_t)h * DH_;
    const size_t vhead = (size_t)bh * ((size_t)DH_ * S_);

#pragma unroll
    for (int t = 0; t < 8; t++) {
        int f = tid + t * 256;
        int r = f >> 5, c4 = f & 31;
        float4 v4 = *(const float4*)(q + head + (size_t)(q0 + r) * D_ + c4 * 4);
        uint4 u;
        u.x = f2tf32(v4.x); u.y = f2tf32(v4.y);
        u.z = f2tf32(v4.z); u.w = f2tf32(v4.w);
        *(uint4*)(Qs + r * FQ_ST + c4 * 4) = u;
    }
    if (tid < 64) { row_m[tid] = -1e30f; row_l[tid] = 0.f; }

    float4 rk[8], rv[8];
#pragma unroll
    for (int t = 0; t < 8; t++) {
        int f = tid + t * 256;
        int r = f >> 5, c4 = f & 31;
        rk[t] = *(const float4*)(k + head + (size_t)r * D_ + c4 * 4);
        int rr = f >> 4, cc = f & 15;
        rv[t] = *(const float4*)(vt + vhead + (size_t)rr * S_ + cc * 4);
    }

    float oacc[8][4];
#pragma unroll
    for (int i = 0; i < 8; i++)
#pragma unroll
        for (int j = 0; j < 4; j++) oacc[i][j] = 0.f;

    const float scale = 0.08838834764831845f;
    __syncthreads();

    for (int kt = 0; kt < S_ / 64; kt++) {
#pragma unroll
        for (int t = 0; t < 8; t++) {
            int f = tid + t * 256;
            int r = f >> 5, c4 = f & 31;
            uint4 u;
            u.x = f2tf32(rk[t].x); u.y = f2tf32(rk[t].y);
            u.z = f2tf32(rk[t].z); u.w = f2tf32(rk[t].w);
            *(uint4*)(Ks + r * FK_ST + c4 * 4) = u;
            int rr = f >> 4, cc = f & 15;
            uint4 v;
            v.x = f2tf32(rv[t].x); v.y = f2tf32(rv[t].y);
            v.z = f2tf32(rv[t].z); v.w = f2tf32(rv[t].w);
            *(uint4*)(Vs + rr * FV_ST + cc * 4) = v;
        }
        __syncthreads();

        if (kt + 1 < S_ / 64) {
            const int kg = (kt + 1) * 64;
#pragma unroll
            for (int t = 0; t < 8; t++) {
                int f = tid + t * 256;
                int r = f >> 5, c4 = f & 31;
                rk[t] = *(const float4*)(k + head + (size_t)(kg + r) * D_ + c4 * 4);
                int rr = f >> 4, cc = f & 15;
                rv[t] = *(const float4*)(vt + vhead + (size_t)rr * S_ + kg + cc * 4);
            }
        }

        float sacc[4][4];
#pragma unroll
        for (int i = 0; i < 4; i++)
#pragma unroll
            for (int j = 0; j < 4; j++) sacc[i][j] = 0.f;

#pragma unroll
        for (int ks = 0; ks < 16; ks++) {
            const int k0 = ks * 8;
            uint32_t a[4], bq[4][2];
            const int ar = wm * 16 + lq;
            a[0] = __float_as_uint(Qs[(ar    ) * FQ_ST + k0 + lr    ]);
            a[1] = __float_as_uint(Qs[(ar + 8) * FQ_ST + k0 + lr    ]);
            a[2] = __float_as_uint(Qs[(ar    ) * FQ_ST + k0 + lr + 4]);
            a[3] = __float_as_uint(Qs[(ar + 8) * FQ_ST + k0 + lr + 4]);
#pragma unroll
            for (int nb = 0; nb < 4; nb++) {
                const int n = wn * 32 + nb * 8 + lq;
                bq[nb][0] = __float_as_uint(Ks[n * FK_ST + k0 + lr    ]);
                bq[nb][1] = __float_as_uint(Ks[n * FK_ST + k0 + lr + 4]);
            }
#pragma unroll
            for (int nb = 0; nb < 4; nb++) mma_tf32(sacc[nb], a, bq[nb]);
        }

#pragma unroll
        for (int nb = 0; nb < 4; nb++) {
            const int col = wn * 32 + nb * 8 + 2 * lr;
            const int r   = wm * 16 + lq;
            *(float2*)(Ss + (r    ) * FS_ST + col) =
                make_float2(sacc[nb][0] * scale, sacc[nb][1] * scale);
            *(float2*)(Ss + (r + 8) * FS_ST + col) =
                make_float2(sacc[nb][2] * scale, sacc[nb][3] * scale);
        }
        __syncthreads();

        if (tid < 64) {
            const int r = tid;
            float m_old = row_m[r];
            float m_new = m_old;
#pragma unroll 8
            for (int c = 0; c < 64; c++) m_new = fmaxf(m_new, Ss[r * FS_ST + c]);
            float alpha = __expf(m_old - m_new);
            float sum = 0.f;
#pragma unroll 8
            for (int c = 0; c < 64; c++) {
                float p = __expf(Ss[r * FS_ST + c] - m_new);
                Ss[r * FS_ST + c] = p;
                sum += p;
            }
            row_l[r] = row_l[r] * alpha + sum;
            row_m[r] = m_new;
            row_a[r] = alpha;
        }
        __syncthreads();

        {
            const float al0 = row_a[wm * 16 + lq];
            const float al1 = row_a[wm * 16 + lq + 8];
#pragma unroll
            for (int nb = 0; nb < 8; nb++) {
                oacc[nb][0] *= al0; oacc[nb][1] *= al0;
                oacc[nb][2] *= al1; oacc[nb][3] *= al1;
            }
        }
#pragma unroll
        for (int ks = 0; ks < 8; ks++) {
            const int k0 = ks * 8;
            uint32_t a[4], bv[8][2];
            const int ar = wm * 16 + lq;
            a[0] = f2tf32(Ss[(ar    ) * FS_ST + k0 + lr    ]);
            a[1] = f2tf32(Ss[(ar + 8) * FS_ST + k0 + lr    ]);
            a[2] = f2tf32(Ss[(ar    ) * FS_ST + k0 + lr + 4]);
            a[3] = f2tf32(Ss[(ar + 8) * FS_ST + k0 + lr + 4]);
#pragma unroll
            for (int nb = 0; nb < 8; nb++) {
                const int n = wn * 64 + nb * 8 + lq;
                bv[nb][0] = __float_as_uint(Vs[n * FV_ST + k0 + lr    ]);
                bv[nb][1] = __float_as_uint(Vs[n * FV_ST + k0 + lr + 4]);
            }
#pragma unroll
            for (int nb = 0; nb < 8; nb++) mma_tf32(oacc[nb], a, bv[nb]);
        }
        __syncthreads();
    }

    // epilogue: normalize, round to tf32 (out-proj GEMM consumes raw bits)
    const float il0 = 1.f / row_l[wm * 16 + lq];
    const float il1 = 1.f / row_l[wm * 16 + lq + 8];
#pragma unroll
    for (int nb = 0; nb < 8; nb++) {
        const int col = wn * 64 + nb * 8 + 2 * lr;
        const int r   = q0 + wm * 16 + lq;
        float2 w0, w1;
        w0.x = __uint_as_float(f2tf32(oacc[nb][0] * il0));
        w0.y = __uint_as_float(f2tf32(oacc[nb][1] * il0));
        w1.x = __uint_as_float(f2tf32(oacc[nb][2] * il1));
        w1.y = __uint_as_float(f2tf32(oacc[nb][3] * il1));
        *(float2*)(o + head + (size_t)r * D_ + col)       = w0;
        *(float2*)(o + head + (size_t)(r + 8) * D_ + col) = w1;
    }
}

// ---------------- launch ---------------------------------------------------
extern "C" void kernel_launch(void* const* d_in, const int* in_sizes, int n_in,
                              void* d_out, int out_size)
{
    const float* x   = (const float*)d_in[0];
    const float* q_w = (const float*)d_in[1];
    const float* k_w = (const float*)d_in[2];
    const float* v_w = (const float*)d_in[3];
    const float* q_b = (const float*)d_in[4];
    const float* k_b = (const float*)d_in[5];
    const float* v_b = (const float*)d_in[6];
    const float* o_w = (const float*)d_in[7];
    const float* o_b = (const float*)d_in[8];
    float* out = (float*)d_out;

    float *qp, *kp, *vp, *ap, *xr, *wq, *wk, *wv, *wo;
    cudaGetSymbolAddress((void**)&qp, g_q);
    cudaGetSymbolAddress((void**)&kp, g_k);
    cudaGetSymbolAddress((void**)&vp, g_v);
    cudaGetSymbolAddress((void**)&ap, g_att);
    cudaGetSymbolAddress((void**)&xr, g_xr);
    cudaGetSymbolAddress((void**)&wq, g_wq);
    cudaGetSymbolAddress((void**)&wk, g_wk);
    cudaGetSymbolAddress((void**)&wv, g_wv);
    cudaGetSymbolAddress((void**)&wo, g_wo);

    cudaFuncSetAttribute(flash_tc,
                         cudaFuncAttributeMaxDynamicSharedMemorySize, FLASH_BYTES);
    cudaFuncSetAttribute(gemm_tc<1>,
                         cudaFuncAttributeMaxDynamicSharedMemorySize, GEMM_SMEM);
    cudaFuncSetAttribute(gemm_tc<0>,
                         cudaFuncAttributeMaxDynamicSharedMemorySize, GEMM_SMEM);

    // pre-round inputs to tf32
    const int n4x = (M_ * D_) / 4;   // x
    const int n4w = (D_ * D_) / 4;   // weights
    tf32_round_kernel<<<n4x / 256, 256>>>((const float4*)x,   (float4*)xr, n4x);
    tf32_round_kernel<<<n4w / 256, 256>>>((const float4*)q_w, (float4*)wq, n4w);
    tf32_round_kernel<<<n4w / 256, 256>>>((const float4*)k_w, (float4*)wk, n4w);
    tf32_round_kernel<<<n4w / 256, 256>>>((const float4*)v_w, (float4*)wv, n4w);
    tf32_round_kernel<<<n4w / 256, 256>>>((const float4*)o_w, (float4*)wo, n4w);

    // fused QKV projections (z = 0:Q, 1:K, 2:V-transposed)
    gemm_tc<1><<<dim3(D_ / 128, M_ / 128, 3), 256, GEMM_SMEM>>>(
        xr, wq, wk, wv, q_b, k_b, v_b, qp, kp, vp);

    rope_kernel<<<(B_ * S_ * H_ * 64) / 256, 256>>>(qp, kp);

    flash_tc<<<dim3(S_ / 64, B_ * H_), 256, FLASH_BYTES>>>(qp, kp, vp, ap);

    // output projection
    gemm_tc<0><<<dim3(D_ / 128, M_ / 128, 1), 256, GEMM_SMEM>>>(
        ap, wo, wo, wo, o_b, o_b, o_b, out, out, out);
}

// round 8
// speedup vs baseline: 5.1458x; 1.3216x over previous
#include <cuda_runtime.h>
#include <cuda_fp16.h>
#include <cstdint>

#define B_  2
#define S_  2048
#define D_  2048
#define H_  16
#define DH_ 128
#define M_  (B_ * S_)   // 4096

// ---------------- scratch (device globals; no allocation allowed) ----------
__device__ float  g_q[(size_t)M_ * D_];
__device__ float  g_k[(size_t)M_ * D_];
__device__ float  g_v[(size_t)M_ * D_];    // V TRANSPOSED fp32: [(b*16+h)][d][s]
__device__ __half g_xh[(size_t)M_ * D_];   // fp16 x
__device__ __half g_wqh[(size_t)D_ * D_];
__device__ __half g_wkh[(size_t)D_ * D_];
__device__ __half g_wvh[(size_t)D_ * D_];
__device__ __half g_woh[(size_t)D_ * D_];
__device__ __half g_atth[(size_t)M_ * D_]; // fp16 attention output

// =================== helpers ===============================================
__device__ __forceinline__ uint32_t f2tf32(float x) {
    uint32_t r;
    asm("cvt.rna.tf32.f32 %0, %1;" : "=r"(r) : "f"(x));
    return r;
}

__device__ __forceinline__ void mma_tf32(float* d,
                                         const uint32_t* a,
                                         const uint32_t* b) {
    asm volatile(
        "mma.sync.aligned.m16n8k8.row.col.f32.tf32.tf32.f32 "
        "{%0,%1,%2,%3}, {%4,%5,%6,%7}, {%8,%9}, {%0,%1,%2,%3};"
        : "+f"(d[0]), "+f"(d[1]), "+f"(d[2]), "+f"(d[3])
        : "r"(a[0]), "r"(a[1]), "r"(a[2]), "r"(a[3]),
          "r"(b[0]), "r"(b[1]));
}

__device__ __forceinline__ void mma_f16(float* d,
                                        const uint32_t* a,
                                        const uint32_t* b) {
    asm volatile(
        "mma.sync.aligned.m16n8k16.row.col.f32.f16.f16.f32 "
        "{%0,%1,%2,%3}, {%4,%5,%6,%7}, {%8,%9}, {%0,%1,%2,%3};"
        : "+f"(d[0]), "+f"(d[1]), "+f"(d[2]), "+f"(d[3])
        : "r"(a[0]), "r"(a[1]), "r"(a[2]), "r"(a[3]),
          "r"(b[0]), "r"(b[1]));
}

__device__ __forceinline__ void ldsm_x4(uint32_t* r, uint32_t addr) {
    asm volatile("ldmatrix.sync.aligned.m8n8.x4.shared.b16 {%0,%1,%2,%3}, [%4];"
                 : "=r"(r[0]), "=r"(r[1]), "=r"(r[2]), "=r"(r[3]) : "r"(addr));
}
__device__ __forceinline__ void ldsm_x2(uint32_t* r, uint32_t addr) {
    asm volatile("ldmatrix.sync.aligned.m8n8.x2.shared.b16 {%0,%1}, [%2];"
                 : "=r"(r[0]), "=r"(r[1]) : "r"(addr));
}

__device__ __forceinline__ void cp16(uint32_t dst, const void* src) {
    asm volatile("cp.async.cg.shared.global [%0], [%1], 16;" :: "r"(dst), "l"(src));
}
#define CP_COMMIT() asm volatile("cp.async.commit_group;" ::: "memory")
#define CP_WAIT(n)  asm volatile("cp.async.wait_group %0;" :: "n"(n) : "memory")

__device__ __forceinline__ uint32_t smem_u32(const void* p) {
    uint32_t a;
    asm("{ .reg .u64 t; cvta.to.shared.u64 t, %1; cvt.u32.u64 %0, t; }"
        : "=r"(a) : "l"(p));
    return a;
}

// ---------------- fp32 -> fp16 conversion ----------------------------------
struct alignas(8) H4 { __half2 a, b; };
__global__ void f32to16_kernel(const float4* __restrict__ in,
                               H4* __restrict__ out, int n4)
{
    int i = blockIdx.x * blockDim.x + threadIdx.x;
    if (i >= n4) return;
    float4 v = in[i];
    H4 h;
    h.a = __floats2half2_rn(v.x, v.y);
    h.b = __floats2half2_rn(v.z, v.w);
    out[i] = h;
}

// =================== fp16 cp.async GEMM ====================================
// C[m,n] = sum_k A[m,k]*W[n,k] + bias[n].  A,W fp16; accum+epilogue fp32.
// CTA 128x128, BK=64 halves (128B rows), 8 warps (2x4), warp tile 64x32.
// 3 smem stages; ldmatrix fragments; XOR-swizzled 16B units.
#define HSTG_BY   32768                 // A tile 16KB + B tile 16KB
#define GEMM_SMEM (3 * HSTG_BY)

__device__ __forceinline__ void issue_chunk_h(uint32_t sdst,
                                              const __half* __restrict__ A,
                                              const __half* __restrict__ W,
                                              int row0, int col0, int kb, int tid)
{
#pragma unroll
    for (int i = 0; i < 4; i++) {
        int f = tid + i * 256;          // 0..1023
        int row = f >> 3, c = f & 7;
        uint32_t doff = (uint32_t)(row * 128 + ((c ^ (row & 7)) * 16));
        cp16(sdst + doff,         A + (size_t)(row0 + row) * D_ + kb + c * 8);
        cp16(sdst + 16384 + doff, W + (size_t)(col0 + row) * D_ + kb + c * 8);
    }
    CP_COMMIT();
}

__device__ __forceinline__ void compute_chunk_h(uint32_t sbase,
                                                int wm, int wn, int lane,
                                                float acc[4][4][4])
{
    const uint32_t Ab = sbase;
    const uint32_t Bb = sbase + 16384;
    const int g  = lane >> 3;           // 0..3
    const int l8 = lane & 7;
#pragma unroll
    for (int ks = 0; ks < 4; ks++) {
        uint32_t afr[4][4], bfr[4][2];
#pragma unroll
        for (int mb = 0; mb < 4; mb++) {
            const int r = wm * 64 + mb * 16 + ((g & 1) << 3) + l8;
            const int u = 2 * ks + (g >> 1);
            ldsm_x4(afr[mb], Ab + r * 128 + ((u ^ (r & 7)) * 16));
        }
#pragma unroll
        for (int nb = 0; nb < 4; nb++) {
            const int r = wn * 32 + nb * 8 + l8;
            const int u = 2 * ks + ((lane >> 3) & 1);
            ldsm_x2(bfr[nb], Bb + r * 128 + ((u ^ (r & 7)) * 16));
        }
#pragma unroll
        for (int mb = 0; mb < 4; mb++)
#pragma unroll
            for (int nb = 0; nb < 4; nb++)
                mma_f16(acc[mb][nb], afr[mb], bfr[nb]);
    }
}

// FUSED=1: grid.z in {0,1,2}; z==2 writes V transposed fp32.
template <int FUSED>
__global__ __launch_bounds__(256, 2)
void gemm_f16(const __half* __restrict__ A,
              const __half* __restrict__ W0, const __half* __restrict__ W1,
              const __half* __restrict__ W2,
              const float* __restrict__ b0, const float* __restrict__ b1,
              const float* __restrict__ b2,
              float* __restrict__ C0, float* __restrict__ C1,
              float* __restrict__ C2)
{
    extern __shared__ char dsm[];
    const uint32_t s_u32 = smem_u32(dsm);

    const int z = FUSED ? blockIdx.z : 0;
    const __half* W    = (z == 0) ? W0 : (z == 1) ? W1 : W2;
    const float*  bias = (z == 0) ? b0 : (z == 1) ? b1 : b2;
    float*        C    = (z == 0) ? C0 : (z == 1) ? C1 : C2;

    const int tid  = threadIdx.x;
    const int wid  = tid >> 5;
    const int lane = tid & 31;
    const int wm   = wid >> 2;
    const int wn   = wid & 3;
    const int lq   = lane >> 2;
    const int lr   = lane & 3;
    const int row0 = blockIdx.y << 7;
    const int col0 = blockIdx.x << 7;

    float acc[4][4][4];
#pragma unroll
    for (int i = 0; i < 4; i++)
#pragma unroll
        for (int j = 0; j < 4; j++)
#pragma unroll
            for (int r = 0; r < 4; r++) acc[i][j][r] = 0.f;

    const int NCH = D_ / 64;   // 32

    issue_chunk_h(s_u32,           A, W, row0, col0, 0,  tid);
    issue_chunk_h(s_u32 + HSTG_BY, A, W, row0, col0, 64, tid);

    for (int ch = 0; ch < NCH - 2; ch++) {
        issue_chunk_h(s_u32 + ((ch + 2) % 3) * HSTG_BY, A, W, row0, col0,
                      (ch + 2) * 64, tid);
        CP_WAIT(2);
        __syncthreads();
        compute_chunk_h(s_u32 + (ch % 3) * HSTG_BY, wm, wn, lane, acc);
        __syncthreads();
    }
    CP_WAIT(1);
    __syncthreads();
    compute_chunk_h(s_u32 + ((NCH - 2) % 3) * HSTG_BY, wm, wn, lane, acc);
    __syncthreads();
    CP_WAIT(0);
    __syncthreads();
    compute_chunk_h(s_u32 + ((NCH - 1) % 3) * HSTG_BY, wm, wn, lane, acc);

    if (FUSED && z == 2) {
        // V transposed epilogue: out[(b*16+h)][d][s], h = blockIdx.x
        const int bidx = row0 >> 11;
        const size_t vbase = ((size_t)bidx * 16 + blockIdx.x) * ((size_t)DH_ * S_);
#pragma unroll
        for (int mb = 0; mb < 4; mb++) {
#pragma unroll
            for (int nb = 0; nb < 4; nb++) {
                const int col = wn * 32 + nb * 8 + lr * 2;
                const float2 bv = *(const float2*)(bias + col0 + col);
                const int r0 = row0 + wm * 64 + mb * 16 + lq;
                const int s0 = r0 & (S_ - 1);
                C[vbase + (size_t)(col    ) * S_ + s0]     = acc[mb][nb][0] + bv.x;
                C[vbase + (size_t)(col + 1) * S_ + s0]     = acc[mb][nb][1] + bv.y;
                C[vbase + (size_t)(col    ) * S_ + s0 + 8] = acc[mb][nb][2] + bv.x;
                C[vbase + (size_t)(col + 1) * S_ + s0 + 8] = acc[mb][nb][3] + bv.y;
            }
        }
    } else {
#pragma unroll
        for (int mb = 0; mb < 4; mb++) {
#pragma unroll
            for (int nb = 0; nb < 4; nb++) {
                const int col = col0 + wn * 32 + nb * 8 + lr * 2;
                const float2 bv = *(const float2*)(bias + col);
                const int r0 = row0 + wm * 64 + mb * 16 + lq;
                float2 o0, o1;
                o0.x = acc[mb][nb][0] + bv.x;
                o0.y = acc[mb][nb][1] + bv.y;
                o1.x = acc[mb][nb][2] + bv.x;
                o1.y = acc[mb][nb][3] + bv.y;
                *(float2*)(C + (size_t)r0 * D_ + col)       = o0;
                *(float2*)(C + (size_t)(r0 + 8) * D_ + col) = o1;
            }
        }
    }
}

// ---------------- RoPE (in-place on q and k, fp32) -------------------------
__global__ void rope_kernel(float* __restrict__ q, float* __restrict__ k)
{
    int idx = blockIdx.x * blockDim.x + threadIdx.x;
    int d0 = idx & 63;
    int h  = (idx >> 6) & (H_ - 1);
    int s  = (idx >> 10) & (S_ - 1);
    int b  = idx >> 21;

    float inv = exp2f(-(float)d0 * (13.287712379549449f / 64.f));
    float ang = (float)s * inv;
    float sn, cs;
    sincosf(ang, &sn, &cs);

    size_t base = ((size_t)(b * S_ + s) * D_) + (size_t)h * DH_ + d0;

    float q1 = q[base], q2 = q[base + 64];
    q[base]      = q1 * cs - q2 * sn;
    q[base + 64] = q2 * cs + q1 * sn;

    float k1 = k[base], k2 = k[base + 64];
    k[base]      = k1 * cs - k2 * sn;
    k[base + 64] = k2 * cs + k1 * sn;
}

// ---------------- Flash attention (tf32 tensor-core, fp16 output) ----------
#define FQ_ST 132
#define FK_ST 132
#define FV_ST 68
#define FS_ST 68
#define FLASH_FLOATS (64*FQ_ST + 64*FK_ST + 128*FV_ST + 64*FS_ST + 3*64)
#define FLASH_BYTES  (FLASH_FLOATS * 4)

__global__ __launch_bounds__(256)
void flash_tc(const float* __restrict__ q, const float* __restrict__ k,
              const float* __restrict__ vt, __half* __restrict__ o)
{
    extern __shared__ float sm[];
    float* Qs    = sm;
    float* Ks    = Qs + 64 * FQ_ST;
    float* Vs    = Ks + 64 * FK_ST;
    float* Ss    = Vs + 128 * FV_ST;
    float* row_m = Ss + 64 * FS_ST;
    float* row_l = row_m + 64;
    float* row_a = row_l + 64;

    const int tid  = threadIdx.x;
    const int wid  = tid >> 5;
    const int lane = tid & 31;
    const int lq   = lane >> 2;
    const int lr   = lane & 3;
    const int wm   = wid & 3;
    const int wn   = wid >> 2;
    const int q0   = blockIdx.x * 64;
    const int bh   = blockIdx.y;
    const int b    = bh >> 4, h = bh & 15;
    const size_t head  = (size_t)b * S_ * D_ + (size_t)h * DH_;
    const size_t vhead = (size_t)bh * ((size_t)DH_ * S_);

#pragma unroll
    for (int t = 0; t < 8; t++) {
        int f = tid + t * 256;
        int r = f >> 5, c4 = f & 31;
        float4 v4 = *(const float4*)(q + head + (size_t)(q0 + r) * D_ + c4 * 4);
        uint4 u;
        u.x = f2tf32(v4.x); u.y = f2tf32(v4.y);
        u.z = f2tf32(v4.z); u.w = f2tf32(v4.w);
        *(uint4*)(Qs + r * FQ_ST + c4 * 4) = u;
    }
    if (tid < 64) { row_m[tid] = -1e30f; row_l[tid] = 0.f; }

    float4 rk[8], rv[8];
#pragma unroll
    for (int t = 0; t < 8; t++) {
        int f = tid + t * 256;
        int r = f >> 5, c4 = f & 31;
        rk[t] = *(const float4*)(k + head + (size_t)r * D_ + c4 * 4);
        int rr = f >> 4, cc = f & 15;
        rv[t] = *(const float4*)(vt + vhead + (size_t)rr * S_ + cc * 4);
    }

    float oacc[8][4];
#pragma unroll
    for (int i = 0; i < 8; i++)
#pragma unroll
        for (int j = 0; j < 4; j++) oacc[i][j] = 0.f;

    const float scale = 0.08838834764831845f;
    __syncthreads();

    for (int kt = 0; kt < S_ / 64; kt++) {
#pragma unroll
        for (int t = 0; t < 8; t++) {
            int f = tid + t * 256;
            int r = f >> 5, c4 = f & 31;
            uint4 u;
            u.x = f2tf32(rk[t].x); u.y = f2tf32(rk[t].y);
            u.z = f2tf32(rk[t].z); u.w = f2tf32(rk[t].w);
            *(uint4*)(Ks + r * FK_ST + c4 * 4) = u;
            int rr = f >> 4, cc = f & 15;
            uint4 v;
            v.x = f2tf32(rv[t].x); v.y = f2tf32(rv[t].y);
            v.z = f2tf32(rv[t].z); v.w = f2tf32(rv[t].w);
            *(uint4*)(Vs + rr * FV_ST + cc * 4) = v;
        }
        __syncthreads();

        if (kt + 1 < S_ / 64) {
            const int kg = (kt + 1) * 64;
#pragma unroll
            for (int t = 0; t < 8; t++) {
                int f = tid + t * 256;
                int r = f >> 5, c4 = f & 31;
                rk[t] = *(const float4*)(k + head + (size_t)(kg + r) * D_ + c4 * 4);
                int rr = f >> 4, cc = f & 15;
                rv[t] = *(const float4*)(vt + vhead + (size_t)rr * S_ + kg + cc * 4);
            }
        }

        float sacc[4][4];
#pragma unroll
        for (int i = 0; i < 4; i++)
#pragma unroll
            for (int j = 0; j < 4; j++) sacc[i][j] = 0.f;

#pragma unroll
        for (int ks = 0; ks < 16; ks++) {
            const int k0 = ks * 8;
            uint32_t a[4], bq[4][2];
            const int ar = wm * 16 + lq;
            a[0] = __float_as_uint(Qs[(ar    ) * FQ_ST + k0 + lr    ]);
            a[1] = __float_as_uint(Qs[(ar + 8) * FQ_ST + k0 + lr    ]);
            a[2] = __float_as_uint(Qs[(ar    ) * FQ_ST + k0 + lr + 4]);
            a[3] = __float_as_uint(Qs[(ar + 8) * FQ_ST + k0 + lr + 4]);
#pragma unroll
            for (int nb = 0; nb < 4; nb++) {
                const int n = wn * 32 + nb * 8 + lq;
                bq[nb][0] = __float_as_uint(Ks[n * FK_ST + k0 + lr    ]);
                bq[nb][1] = __float_as_uint(Ks[n * FK_ST + k0 + lr + 4]);
            }
#pragma unroll
            for (int nb = 0; nb < 4; nb++) mma_tf32(sacc[nb], a, bq[nb]);
        }

#pragma unroll
        for (int nb = 0; nb < 4; nb++) {
            const int col = wn * 32 + nb * 8 + 2 * lr;
            const int r   = wm * 16 + lq;
            *(float2*)(Ss + (r    ) * FS_ST + col) =
                make_float2(sacc[nb][0] * scale, sacc[nb][1] * scale);
            *(float2*)(Ss + (r + 8) * FS_ST + col) =
                make_float2(sacc[nb][2] * scale, sacc[nb][3] * scale);
        }
        __syncthreads();

        if (tid < 64) {
            const int r = tid;
            float m_old = row_m[r];
            float m_new = m_old;
#pragma unroll 8
            for (int c = 0; c < 64; c++) m_new = fmaxf(m_new, Ss[r * FS_ST + c]);
            float alpha = __expf(m_old - m_new);
            float sum = 0.f;
#pragma unroll 8
            for (int c = 0; c < 64; c++) {
                float p = __expf(Ss[r * FS_ST + c] - m_new);
                Ss[r * FS_ST + c] = p;
                sum += p;
            }
            row_l[r] = row_l[r] * alpha + sum;
            row_m[r] = m_new;
            row_a[r] = alpha;
        }
        __syncthreads();

        {
            const float al0 = row_a[wm * 16 + lq];
            const float al1 = row_a[wm * 16 + lq + 8];
#pragma unroll
            for (int nb = 0; nb < 8; nb++) {
                oacc[nb][0] *= al0; oacc[nb][1] *= al0;
                oacc[nb][2] *= al1; oacc[nb][3] *= al1;
            }
        }
#pragma unroll
        for (int ks = 0; ks < 8; ks++) {
            const int k0 = ks * 8;
            uint32_t a[4], bv[8][2];
            const int ar = wm * 16 + lq;
            a[0] = f2tf32(Ss[(ar    ) * FS_ST + k0 + lr    ]);
            a[1] = f2tf32(Ss[(ar + 8) * FS_ST + k0 + lr    ]);
            a[2] = f2tf32(Ss[(ar    ) * FS_ST + k0 + lr + 4]);
            a[3] = f2tf32(Ss[(ar + 8) * FS_ST + k0 + lr + 4]);
#pragma unroll
            for (int nb = 0; nb < 8; nb++) {
                const int n = wn * 64 + nb * 8 + lq;
                bv[nb][0] = __float_as_uint(Vs[n * FV_ST + k0 + lr    ]);
                bv[nb][1] = __float_as_uint(Vs[n * FV_ST + k0 + lr + 4]);
            }
#pragma unroll
            for (int nb = 0; nb < 8; nb++) mma_tf32(oacc[nb], a, bv[nb]);
        }
        __syncthreads();
    }

    // epilogue: normalize, write fp16 att (feeds fp16 out-proj GEMM)
    const float il0 = 1.f / row_l[wm * 16 + lq];
    const float il1 = 1.f / row_l[wm * 16 + lq + 8];
#pragma unroll
    for (int nb = 0; nb < 8; nb++) {
        const int col = wn * 64 + nb * 8 + 2 * lr;
        const int r   = q0 + wm * 16 + lq;
        *(__half2*)(o + head + (size_t)r * D_ + col) =
            __floats2half2_rn(oacc[nb][0] * il0, oacc[nb][1] * il0);
        *(__half2*)(o + head + (size_t)(r + 8) * D_ + col) =
            __floats2half2_rn(oacc[nb][2] * il1, oacc[nb][3] * il1);
    }
}

// ---------------- launch ---------------------------------------------------
extern "C" void kernel_launch(void* const* d_in, const int* in_sizes, int n_in,
                              void* d_out, int out_size)
{
    const float* x   = (const float*)d_in[0];
    const float* q_w = (const float*)d_in[1];
    const float* k_w = (const float*)d_in[2];
    const float* v_w = (const float*)d_in[3];
    const float* q_b = (const float*)d_in[4];
    const float* k_b = (const float*)d_in[5];
    const float* v_b = (const float*)d_in[6];
    const float* o_w = (const float*)d_in[7];
    const float* o_b = (const float*)d_in[8];
    float* out = (float*)d_out;

    float  *qp, *kp, *vp;
    __half *xh, *wqh, *wkh, *wvh, *woh, *ath;
    cudaGetSymbolAddress((void**)&qp,  g_q);
    cudaGetSymbolAddress((void**)&kp,  g_k);
    cudaGetSymbolAddress((void**)&vp,  g_v);
    cudaGetSymbolAddress((void**)&xh,  g_xh);
    cudaGetSymbolAddress((void**)&wqh, g_wqh);
    cudaGetSymbolAddress((void**)&wkh, g_wkh);
    cudaGetSymbolAddress((void**)&wvh, g_wvh);
    cudaGetSymbolAddress((void**)&woh, g_woh);
    cudaGetSymbolAddress((void**)&ath, g_atth);

    cudaFuncSetAttribute(flash_tc,
                         cudaFuncAttributeMaxDynamicSharedMemorySize, FLASH_BYTES);
    cudaFuncSetAttribute(gemm_f16<1>,
                         cudaFuncAttributeMaxDynamicSharedMemorySize, GEMM_SMEM);
    cudaFuncSetAttribute(gemm_f16<0>,
                         cudaFuncAttributeMaxDynamicSharedMemorySize, GEMM_SMEM);

    // fp32 -> fp16 conversions
    const int n4x = (M_ * D_) / 4;
    const int n4w = (D_ * D_) / 4;
    f32to16_kernel<<<n4x / 256, 256>>>((const float4*)x,   (H4*)xh,  n4x);
    f32to16_kernel<<<n4w / 256, 256>>>((const float4*)q_w, (H4*)wqh, n4w);
    f32to16_kernel<<<n4w / 256, 256>>>((const float4*)k_w, (H4*)wkh, n4w);
    f32to16_kernel<<<n4w / 256, 256>>>((const float4*)v_w, (H4*)wvh, n4w);
    f32to16_kernel<<<n4w / 256, 256>>>((const float4*)o_w, (H4*)woh, n4w);

    // fused QKV projections (z = 0:Q, 1:K, 2:V-transposed)
    gemm_f16<1><<<dim3(D_ / 128, M_ / 128, 3), 256, GEMM_SMEM>>>(
        xh, wqh, wkh, wvh, q_b, k_b, v_b, qp, kp, vp);

    rope_kernel<<<(B_ * S_ * H_ * 64) / 256, 256>>>(qp, kp);

    flash_tc<<<dim3(S_ / 64, B_ * H_), 256, FLASH_BYTES>>>(qp, kp, vp, ath);

    // output projection (fp16 att input)
    gemm_f16<0><<<dim3(D_ / 128, M_ / 128, 1), 256, GEMM_SMEM>>>(
        ath, woh, woh, woh, o_b, o_b, o_b, out, out, out);
}

// round 9
// speedup vs baseline: 5.6986x; 1.1074x over previous
#include <cuda_runtime.h>
#include <cuda_fp16.h>
#include <cstdint>

#define B_  2
#define S_  2048
#define D_  2048
#define H_  16
#define DH_ 128
#define M_  (B_ * S_)   // 4096

// ---------------- scratch (device globals; no allocation allowed) ----------
__device__ float  g_q[(size_t)M_ * D_];    // fp32 Q (pre-rope)
__device__ float  g_k[(size_t)M_ * D_];    // fp32 K (pre-rope)
__device__ __half g_qh[(size_t)M_ * D_];   // fp16 Q (post-rope)
__device__ __half g_kh[(size_t)M_ * D_];   // fp16 K (post-rope)
__device__ __half g_vh[(size_t)M_ * D_];   // fp16 V TRANSPOSED [(b*16+h)][d][s]
__device__ __half g_xh[(size_t)M_ * D_];   // fp16 x
__device__ __half g_wqh[(size_t)D_ * D_];
__device__ __half g_wkh[(size_t)D_ * D_];
__device__ __half g_wvh[(size_t)D_ * D_];
__device__ __half g_woh[(size_t)D_ * D_];
__device__ __half g_atth[(size_t)M_ * D_]; // fp16 attention output

// =================== helpers ===============================================
__device__ __forceinline__ void mma_f16(float* d,
                                        const uint32_t* a,
                                        const uint32_t* b) {
    asm volatile(
        "mma.sync.aligned.m16n8k16.row.col.f32.f16.f16.f32 "
        "{%0,%1,%2,%3}, {%4,%5,%6,%7}, {%8,%9}, {%0,%1,%2,%3};"
        : "+f"(d[0]), "+f"(d[1]), "+f"(d[2]), "+f"(d[3])
        : "r"(a[0]), "r"(a[1]), "r"(a[2]), "r"(a[3]),
          "r"(b[0]), "r"(b[1]));
}

__device__ __forceinline__ void ldsm_x4(uint32_t* r, uint32_t addr) {
    asm volatile("ldmatrix.sync.aligned.m8n8.x4.shared.b16 {%0,%1,%2,%3}, [%4];"
                 : "=r"(r[0]), "=r"(r[1]), "=r"(r[2]), "=r"(r[3]) : "r"(addr));
}
__device__ __forceinline__ void ldsm_x2(uint32_t* r, uint32_t addr) {
    asm volatile("ldmatrix.sync.aligned.m8n8.x2.shared.b16 {%0,%1}, [%2];"
                 : "=r"(r[0]), "=r"(r[1]) : "r"(addr));
}

__device__ __forceinline__ void cp16(uint32_t dst, const void* src) {
    asm volatile("cp.async.cg.shared.global [%0], [%1], 16;" :: "r"(dst), "l"(src));
}
#define CP_COMMIT() asm volatile("cp.async.commit_group;" ::: "memory")
#define CP_WAIT(n)  asm volatile("cp.async.wait_group %0;" :: "n"(n) : "memory")

__device__ __forceinline__ uint32_t smem_u32(const void* p) {
    uint32_t a;
    asm("{ .reg .u64 t; cvta.to.shared.u64 t, %1; cvt.u32.u64 %0, t; }"
        : "=r"(a) : "l"(p));
    return a;
}

// ---------------- fp32 -> fp16 conversion ----------------------------------
struct alignas(8) H4 { __half2 a, b; };
__global__ void f32to16_kernel(const float4* __restrict__ in,
                               H4* __restrict__ out, int n4)
{
    int i = blockIdx.x * blockDim.x + threadIdx.x;
    if (i >= n4) return;
    float4 v = in[i];
    H4 h;
    h.a = __floats2half2_rn(v.x, v.y);
    h.b = __floats2half2_rn(v.z, v.w);
    out[i] = h;
}

// =================== fp16 cp.async GEMM ====================================
// CTA 128x128, BK=64 halves, 8 warps (2x4), warp tile 64x32, 3 smem stages.
#define HSTG_BY   32768
#define GEMM_SMEM (3 * HSTG_BY)

__device__ __forceinline__ void issue_chunk_h(uint32_t sdst,
                                              const __half* __restrict__ A,
                                              const __half* __restrict__ W,
                                              int row0, int col0, int kb, int tid)
{
#pragma unroll
    for (int i = 0; i < 4; i++) {
        int f = tid + i * 256;
        int row = f >> 3, c = f & 7;
        uint32_t doff = (uint32_t)(row * 128 + ((c ^ (row & 7)) * 16));
        cp16(sdst + doff,         A + (size_t)(row0 + row) * D_ + kb + c * 8);
        cp16(sdst + 16384 + doff, W + (size_t)(col0 + row) * D_ + kb + c * 8);
    }
    CP_COMMIT();
}

__device__ __forceinline__ void compute_chunk_h(uint32_t sbase,
                                                int wm, int wn, int lane,
                                                float acc[4][4][4])
{
    const uint32_t Ab = sbase;
    const uint32_t Bb = sbase + 16384;
    const int g  = lane >> 3;
    const int l8 = lane & 7;
#pragma unroll
    for (int ks = 0; ks < 4; ks++) {
        uint32_t afr[4][4], bfr[4][2];
#pragma unroll
        for (int mb = 0; mb < 4; mb++) {
            const int r = wm * 64 + mb * 16 + ((g & 1) << 3) + l8;
            const int u = 2 * ks + (g >> 1);
            ldsm_x4(afr[mb], Ab + r * 128 + ((u ^ (r & 7)) * 16));
        }
#pragma unroll
        for (int nb = 0; nb < 4; nb++) {
            const int r = wn * 32 + nb * 8 + l8;
            const int u = 2 * ks + ((lane >> 3) & 1);
            ldsm_x2(bfr[nb], Bb + r * 128 + ((u ^ (r & 7)) * 16));
        }
#pragma unroll
        for (int mb = 0; mb < 4; mb++)
#pragma unroll
            for (int nb = 0; nb < 4; nb++)
                mma_f16(acc[mb][nb], afr[mb], bfr[nb]);
    }
}

// FUSED=1: z in {0,1,2}; z<2 writes fp32 C, z==2 writes fp16 V transposed.
template <int FUSED>
__global__ __launch_bounds__(256, 2)
void gemm_f16(const __half* __restrict__ A,
              const __half* __restrict__ W0, const __half* __restrict__ W1,
              const __half* __restrict__ W2,
              const float* __restrict__ b0, const float* __restrict__ b1,
              const float* __restrict__ b2,
              float* __restrict__ C0, float* __restrict__ C1,
              __half* __restrict__ CV)
{
    extern __shared__ char dsm[];
    const uint32_t s_u32 = smem_u32(dsm);

    const int z = FUSED ? blockIdx.z : 0;
    const __half* W    = (z == 0) ? W0 : (z == 1) ? W1 : W2;
    const float*  bias = (z == 0) ? b0 : (z == 1) ? b1 : b2;
    float*        C    = (z == 0) ? C0 : C1;

    const int tid  = threadIdx.x;
    const int wid  = tid >> 5;
    const int lane = tid & 31;
    const int wm   = wid >> 2;
    const int wn   = wid & 3;
    const int lq   = lane >> 2;
    const int lr   = lane & 3;
    const int row0 = blockIdx.y << 7;
    const int col0 = blockIdx.x << 7;

    float acc[4][4][4];
#pragma unroll
    for (int i = 0; i < 4; i++)
#pragma unroll
        for (int j = 0; j < 4; j++)
#pragma unroll
            for (int r = 0; r < 4; r++) acc[i][j][r] = 0.f;

    const int NCH = D_ / 64;   // 32

    issue_chunk_h(s_u32,           A, W, row0, col0, 0,  tid);
    issue_chunk_h(s_u32 + HSTG_BY, A, W, row0, col0, 64, tid);

    for (int ch = 0; ch < NCH - 2; ch++) {
        issue_chunk_h(s_u32 + ((ch + 2) % 3) * HSTG_BY, A, W, row0, col0,
                      (ch + 2) * 64, tid);
        CP_WAIT(2);
        __syncthreads();
        compute_chunk_h(s_u32 + (ch % 3) * HSTG_BY, wm, wn, lane, acc);
        __syncthreads();
    }
    CP_WAIT(1);
    __syncthreads();
    compute_chunk_h(s_u32 + ((NCH - 2) % 3) * HSTG_BY, wm, wn, lane, acc);
    __syncthreads();
    CP_WAIT(0);
    __syncthreads();
    compute_chunk_h(s_u32 + ((NCH - 1) % 3) * HSTG_BY, wm, wn, lane, acc);

    if (FUSED && z == 2) {
        // fp16 V transposed epilogue: out[(b*16+h)][d][s], h = blockIdx.x
        const int bidx = row0 >> 11;
        const size_t vbase = ((size_t)bidx * 16 + blockIdx.x) * ((size_t)DH_ * S_);
#pragma unroll
        for (int mb = 0; mb < 4; mb++) {
#pragma unroll
            for (int nb = 0; nb < 4; nb++) {
                const int col = wn * 32 + nb * 8 + lr * 2;
                const float2 bv = *(const float2*)(bias + col0 + col);
                const int r0 = row0 + wm * 64 + mb * 16 + lq;
                const int s0 = r0 & (S_ - 1);
                CV[vbase + (size_t)(col    ) * S_ + s0]     = __float2half_rn(acc[mb][nb][0] + bv.x);
                CV[vbase + (size_t)(col + 1) * S_ + s0]     = __float2half_rn(acc[mb][nb][1] + bv.y);
                CV[vbase + (size_t)(col    ) * S_ + s0 + 8] = __float2half_rn(acc[mb][nb][2] + bv.x);
                CV[vbase + (size_t)(col + 1) * S_ + s0 + 8] = __float2half_rn(acc[mb][nb][3] + bv.y);
            }
        }
    } else {
#pragma unroll
        for (int mb = 0; mb < 4; mb++) {
#pragma unroll
            for (int nb = 0; nb < 4; nb++) {
                const int col = col0 + wn * 32 + nb * 8 + lr * 2;
                const float2 bv = *(const float2*)(bias + col);
                const int r0 = row0 + wm * 64 + mb * 16 + lq;
                float2 o0, o1;
                o0.x = acc[mb][nb][0] + bv.x;
                o0.y = acc[mb][nb][1] + bv.y;
                o1.x = acc[mb][nb][2] + bv.x;
                o1.y = acc[mb][nb][3] + bv.y;
                *(float2*)(C + (size_t)r0 * D_ + col)       = o0;
                *(float2*)(C + (size_t)(r0 + 8) * D_ + col) = o1;
            }
        }
    }
}

// ---------------- RoPE: fp32 in, fp16 out ----------------------------------
__global__ void rope_kernel(const float* __restrict__ q, const float* __restrict__ k,
                            __half* __restrict__ qh, __half* __restrict__ kh)
{
    int idx = blockIdx.x * blockDim.x + threadIdx.x;
    int d0 = idx & 63;
    int h  = (idx >> 6) & (H_ - 1);
    int s  = (idx >> 10) & (S_ - 1);
    int b  = idx >> 21;

    float inv = exp2f(-(float)d0 * (13.287712379549449f / 64.f));
    float ang = (float)s * inv;
    float sn, cs;
    sincosf(ang, &sn, &cs);

    size_t base = ((size_t)(b * S_ + s) * D_) + (size_t)h * DH_ + d0;

    float q1 = q[base], q2 = q[base + 64];
    qh[base]      = __float2half_rn(q1 * cs - q2 * sn);
    qh[base + 64] = __float2half_rn(q2 * cs + q1 * sn);

    float k1 = k[base], k2 = k[base + 64];
    kh[base]      = __float2half_rn(k1 * cs - k2 * sn);
    kh[base + 64] = __float2half_rn(k2 * cs + k1 * sn);
}

// ---------------- Flash attention (fp16 mma, cp.async pipeline) ------------
// Bq = Bk = 64, Dh = 128, 256 threads = 8 warps: (wm 0..3) x (wn 0..1).
// Q [64][128]h stride 136; K stage [64][128]h stride 136;
// V stage [128 d][64 s]h stride 72; Ss fp32 [64][68]; Ps fp16 [64][72].
#define FQH_ST 136
#define FKH_ST 136
#define FVH_ST 72
#define FSS_ST 68
#define FPS_ST 72
#define Q_BY   (64 * FQH_ST * 2)          // 17408
#define K_BY   (64 * FKH_ST * 2)          // 17408
#define V_BY   (128 * FVH_ST * 2)         // 18432
#define KV_BY  (K_BY + V_BY)              // 35840
#define SS_BY  (64 * FSS_ST * 4)          // 17408
#define PS_BY  (64 * FPS_ST * 2)          // 9216
#define FLASH_BYTES (Q_BY + 2 * KV_BY + SS_BY + PS_BY + 3 * 64 * 4)

__global__ __launch_bounds__(256)
void flash_h(const __half* __restrict__ qh, const __half* __restrict__ kh,
             const __half* __restrict__ vh, __half* __restrict__ o)
{
    extern __shared__ char fsm[];
    const uint32_t Qs  = smem_u32(fsm);
    const uint32_t KV0 = Qs + Q_BY;
    const uint32_t Ssm = KV0 + 2 * KV_BY;
    const uint32_t Psm = Ssm + SS_BY;
    float* Ssf   = (float*)(fsm + (Ssm - Qs) + 0);
    float* row_m = (float*)(fsm + (Psm - Qs) + PS_BY);
    float* row_l = row_m + 64;
    float* row_a = row_l + 64;

    const int tid  = threadIdx.x;
    const int wid  = tid >> 5;
    const int lane = tid & 31;
    const int lq   = lane >> 2;
    const int lr   = lane & 3;
    const int g    = lane >> 3;
    const int l8   = lane & 7;
    const int wm   = wid & 3;     // 0..3
    const int wn   = wid >> 2;    // 0..1
    const int q0   = blockIdx.x * 64;
    const int bh   = blockIdx.y;
    const int b    = bh >> 4, h = bh & 15;
    const size_t head  = (size_t)b * S_ * D_ + (size_t)h * DH_;
    const size_t vhead = (size_t)bh * ((size_t)DH_ * S_);
    const int NT = S_ / 64;

    // ---- issue Q (group), then K/V stage 0 (group)
#pragma unroll
    for (int i = 0; i < 4; i++) {
        int f = tid + i * 256;
        int r = f >> 4, c = f & 15;
        cp16(Qs + r * (FQH_ST * 2) + c * 16,
             qh + head + (size_t)(q0 + r) * D_ + c * 8);
    }
    CP_COMMIT();
    {
#pragma unroll
        for (int i = 0; i < 4; i++) {
            int f = tid + i * 256;
            int r = f >> 4, c = f & 15;
            cp16(KV0 + r * (FKH_ST * 2) + c * 16,
                 kh + head + (size_t)r * D_ + c * 8);
        }
#pragma unroll
        for (int i = 0; i < 4; i++) {
            int f = tid + i * 256;
            int r = f >> 3, c = f & 7;
            cp16(KV0 + K_BY + r * (FVH_ST * 2) + c * 16,
                 vh + vhead + (size_t)r * S_ + c * 8);
        }
        CP_COMMIT();
    }
    if (tid < 64) { row_m[tid] = -1e30f; row_l[tid] = 0.f; }

    float oacc[8][4];
#pragma unroll
    for (int i = 0; i < 8; i++)
#pragma unroll
        for (int j = 0; j < 4; j++) oacc[i][j] = 0.f;

    const float scale = 0.08838834764831845f;

    CP_WAIT(0);
    __syncthreads();

    // ---- hoist Q fragments (8 k-steps x 4 regs)
    uint32_t qfr[8][4];
#pragma unroll
    for (int ks = 0; ks < 8; ks++) {
        const int r = wm * 16 + ((g & 1) << 3) + l8;
        ldsm_x4(qfr[ks], Qs + (r * FQH_ST + ks * 16 + (g >> 1) * 8) * 2);
    }

    for (int kt = 0; kt < NT; kt++) {
        const uint32_t KVc = KV0 + (kt & 1) * KV_BY;
        // ---- prefetch next K/V stage
        if (kt + 1 < NT) {
            const uint32_t KVn = KV0 + ((kt + 1) & 1) * KV_BY;
            const int kg = (kt + 1) * 64;
#pragma unroll
            for (int i = 0; i < 4; i++) {
                int f = tid + i * 256;
                int r = f >> 4, c = f & 15;
                cp16(KVn + r * (FKH_ST * 2) + c * 16,
                     kh + head + (size_t)(kg + r) * D_ + c * 8);
            }
#pragma unroll
            for (int i = 0; i < 4; i++) {
                int f = tid + i * 256;
                int r = f >> 3, c = f & 7;
                cp16(KVn + K_BY + r * (FVH_ST * 2) + c * 16,
                     vh + vhead + (size_t)r * S_ + kg + c * 8);
            }
            CP_COMMIT();
            if (kt > 0) CP_WAIT(1);
        } else {
            CP_WAIT(0);
        }
        __syncthreads();

        // ---- S = Q K^T (warp tile 16x32, m16n8k16)
        float sacc[4][4];
#pragma unroll
        for (int i = 0; i < 4; i++)
#pragma unroll
            for (int j = 0; j < 4; j++) sacc[i][j] = 0.f;

#pragma unroll
        for (int ks = 0; ks < 8; ks++) {
            uint32_t bq[4][2];
#pragma unroll
            for (int nb = 0; nb < 4; nb++) {
                const int n = wn * 32 + nb * 8 + l8;
                ldsm_x2(bq[nb], KVc + (n * FKH_ST + ks * 16 + ((lane >> 3) & 1) * 8) * 2);
            }
#pragma unroll
            for (int nb = 0; nb < 4; nb++) mma_f16(sacc[nb], qfr[ks], bq[nb]);
        }

#pragma unroll
        for (int nb = 0; nb < 4; nb++) {
            const int col = wn * 32 + nb * 8 + 2 * lr;
            const int r   = wm * 16 + lq;
            *(float2*)(Ssf + (r    ) * FSS_ST + col) =
                make_float2(sacc[nb][0] * scale, sacc[nb][1] * scale);
            *(float2*)(Ssf + (r + 8) * FSS_ST + col) =
                make_float2(sacc[nb][2] * scale, sacc[nb][3] * scale);
        }
        __syncthreads();

        // ---- online softmax -> fp16 probs
        if (tid < 64) {
            const int r = tid;
            float m_old = row_m[r];
            float m_new = m_old;
#pragma unroll 8
            for (int c = 0; c < 64; c++) m_new = fmaxf(m_new, Ssf[r * FSS_ST + c]);
            float alpha = __expf(m_old - m_new);
            float sum = 0.f;
            __half* pr = (__half*)(fsm + (Psm - Qs)) + r * FPS_ST;
#pragma unroll 4
            for (int c = 0; c < 64; c += 2) {
                float p0 = __expf(Ssf[r * FSS_ST + c]     - m_new);
                float p1 = __expf(Ssf[r * FSS_ST + c + 1] - m_new);
                *(__half2*)(pr + c) = __floats2half2_rn(p0, p1);
                sum += p0 + p1;
            }
            row_l[r] = row_l[r] * alpha + sum;
            row_m[r] = m_new;
            row_a[r] = alpha;
        }
        __syncthreads();

        // ---- rescale O, then O += P V (warp tile 16x64, m16n8k16)
        {
            const float al0 = row_a[wm * 16 + lq];
            const float al1 = row_a[wm * 16 + lq + 8];
#pragma unroll
            for (int nb = 0; nb < 8; nb++) {
                oacc[nb][0] *= al0; oacc[nb][1] *= al0;
                oacc[nb][2] *= al1; oacc[nb][3] *= al1;
            }
        }
#pragma unroll
        for (int ks = 0; ks < 4; ks++) {
            uint32_t a[4], bv[8][2];
            const int ar = wm * 16 + ((g & 1) << 3) + l8;
            ldsm_x4(a, Psm + (ar * FPS_ST + ks * 16 + (g >> 1) * 8) * 2);
#pragma unroll
            for (int nb = 0; nb < 8; nb++) {
                const int n = wn * 64 + nb * 8 + l8;
                ldsm_x2(bv[nb], KVc + K_BY + (n * FVH_ST + ks * 16 + ((lane >> 3) & 1) * 8) * 2);
            }
#pragma unroll
            for (int nb = 0; nb < 8; nb++) mma_f16(oacc[nb], a, bv[nb]);
        }
        __syncthreads();
    }

    // ---- epilogue: normalize, write fp16 att
    const float il0 = 1.f / row_l[wm * 16 + lq];
    const float il1 = 1.f / row_l[wm * 16 + lq + 8];
#pragma unroll
    for (int nb = 0; nb < 8; nb++) {
        const int col = wn * 64 + nb * 8 + 2 * lr;
        const int r   = q0 + wm * 16 + lq;
        *(__half2*)(o + head + (size_t)r * D_ + col) =
            __floats2half2_rn(oacc[nb][0] * il0, oacc[nb][1] * il0);
        *(__half2*)(o + head + (size_t)(r + 8) * D_ + col) =
            __floats2half2_rn(oacc[nb][2] * il1, oacc[nb][3] * il1);
    }
}

// ---------------- launch ---------------------------------------------------
extern "C" void kernel_launch(void* const* d_in, const int* in_sizes, int n_in,
                              void* d_out, int out_size)
{
    const float* x   = (const float*)d_in[0];
    const float* q_w = (const float*)d_in[1];
    const float* k_w = (const float*)d_in[2];
    const float* v_w = (const float*)d_in[3];
    const float* q_b = (const float*)d_in[4];
    const float* k_b = (const float*)d_in[5];
    const float* v_b = (const float*)d_in[6];
    const float* o_w = (const float*)d_in[7];
    const float* o_b = (const float*)d_in[8];
    float* out = (float*)d_out;

    float  *qp, *kp;
    __half *qhp, *khp, *vhp, *xh, *wqh, *wkh, *wvh, *woh, *ath;
    cudaGetSymbolAddress((void**)&qp,  g_q);
    cudaGetSymbolAddress((void**)&kp,  g_k);
    cudaGetSymbolAddress((void**)&qhp, g_qh);
    cudaGetSymbolAddress((void**)&khp, g_kh);
    cudaGetSymbolAddress((void**)&vhp, g_vh);
    cudaGetSymbolAddress((void**)&xh,  g_xh);
    cudaGetSymbolAddress((void**)&wqh, g_wqh);
    cudaGetSymbolAddress((void**)&wkh, g_wkh);
    cudaGetSymbolAddress((void**)&wvh, g_wvh);
    cudaGetSymbolAddress((void**)&woh, g_woh);
    cudaGetSymbolAddress((void**)&ath, g_atth);

    cudaFuncSetAttribute(flash_h,
                         cudaFuncAttributeMaxDynamicSharedMemorySize, FLASH_BYTES);
    cudaFuncSetAttribute(gemm_f16<1>,
                         cudaFuncAttributeMaxDynamicSharedMemorySize, GEMM_SMEM);
    cudaFuncSetAttribute(gemm_f16<0>,
                         cudaFuncAttributeMaxDynamicSharedMemorySize, GEMM_SMEM);

    // fp32 -> fp16 conversions
    const int n4x = (M_ * D_) / 4;
    const int n4w = (D_ * D_) / 4;
    f32to16_kernel<<<n4x / 256, 256>>>((const float4*)x,   (H4*)xh,  n4x);
    f32to16_kernel<<<n4w / 256, 256>>>((const float4*)q_w, (H4*)wqh, n4w);
    f32to16_kernel<<<n4w / 256, 256>>>((const float4*)k_w, (H4*)wkh, n4w);
    f32to16_kernel<<<n4w / 256, 256>>>((const float4*)v_w, (H4*)wvh, n4w);
    f32to16_kernel<<<n4w / 256, 256>>>((const float4*)o_w, (H4*)woh, n4w);

    // fused QKV projections (z = 0:Q fp32, 1:K fp32, 2:V fp16 transposed)
    gemm_f16<1><<<dim3(D_ / 128, M_ / 128, 3), 256, GEMM_SMEM>>>(
        xh, wqh, wkh, wvh, q_b, k_b, v_b, qp, kp, vhp);

    rope_kernel<<<(B_ * S_ * H_ * 64) / 256, 256>>>(qp, kp, qhp, khp);

    flash_h<<<dim3(S_ / 64, B_ * H_), 256, FLASH_BYTES>>>(qhp, khp, vhp, ath);

    // output projection (fp16 att input, fp32 out)
    gemm_f16<0><<<dim3(D_ / 128, M_ / 128, 1), 256, GEMM_SMEM>>>(
        ath, woh, woh, woh, o_b, o_b, o_b, out, out, (__half*)nullptr);
}

// round 10
// speedup vs baseline: 9.4846x; 1.6644x over previous
#include <cuda_runtime.h>
#include <cuda_fp16.h>
#include <cstdint>

#define B_  2
#define S_  2048
#define D_  2048
#define H_  16
#define DH_ 128
#define M_  (B_ * S_)   // 4096

// ---------------- scratch (device globals; no allocation allowed) ----------
__device__ float  g_q[(size_t)M_ * D_];    // fp32 Q (pre-rope)
__device__ float  g_k[(size_t)M_ * D_];    // fp32 K (pre-rope)
__device__ __half g_qh[(size_t)M_ * D_];   // fp16 Q (post-rope, pre-scaled)
__device__ __half g_kh[(size_t)M_ * D_];   // fp16 K (post-rope)
__device__ __half g_vh[(size_t)M_ * D_];   // fp16 V TRANSPOSED [(b*16+h)][d][s]
__device__ __half g_xh[(size_t)M_ * D_];   // fp16 x
__device__ __half g_wqh[(size_t)D_ * D_];
__device__ __half g_wkh[(size_t)D_ * D_];
__device__ __half g_wvh[(size_t)D_ * D_];
__device__ __half g_woh[(size_t)D_ * D_];
__device__ __half g_atth[(size_t)M_ * D_]; // fp16 attention output

// =================== helpers ===============================================
__device__ __forceinline__ void mma_f16(float* d,
                                        const uint32_t* a,
                                        const uint32_t* b) {
    asm volatile(
        "mma.sync.aligned.m16n8k16.row.col.f32.f16.f16.f32 "
        "{%0,%1,%2,%3}, {%4,%5,%6,%7}, {%8,%9}, {%0,%1,%2,%3};"
        : "+f"(d[0]), "+f"(d[1]), "+f"(d[2]), "+f"(d[3])
        : "r"(a[0]), "r"(a[1]), "r"(a[2]), "r"(a[3]),
          "r"(b[0]), "r"(b[1]));
}

__device__ __forceinline__ void ldsm_x4(uint32_t* r, uint32_t addr) {
    asm volatile("ldmatrix.sync.aligned.m8n8.x4.shared.b16 {%0,%1,%2,%3}, [%4];"
                 : "=r"(r[0]), "=r"(r[1]), "=r"(r[2]), "=r"(r[3]) : "r"(addr));
}
__device__ __forceinline__ void ldsm_x2(uint32_t* r, uint32_t addr) {
    asm volatile("ldmatrix.sync.aligned.m8n8.x2.shared.b16 {%0,%1}, [%2];"
                 : "=r"(r[0]), "=r"(r[1]) : "r"(addr));
}

__device__ __forceinline__ void cp16(uint32_t dst, const void* src) {
    asm volatile("cp.async.cg.shared.global [%0], [%1], 16;" :: "r"(dst), "l"(src));
}
#define CP_COMMIT() asm volatile("cp.async.commit_group;" ::: "memory")
#define CP_WAIT(n)  asm volatile("cp.async.wait_group %0;" :: "n"(n) : "memory")

__device__ __forceinline__ uint32_t smem_u32(const void* p) {
    uint32_t a;
    asm("{ .reg .u64 t; cvta.to.shared.u64 t, %1; cvt.u32.u64 %0, t; }"
        : "=r"(a) : "l"(p));
    return a;
}

// ---------------- fp32 -> fp16 conversion ----------------------------------
struct alignas(8) H4 { __half2 a, b; };
__global__ void f32to16_kernel(const float4* __restrict__ in,
                               H4* __restrict__ out, int n4)
{
    int i = blockIdx.x * blockDim.x + threadIdx.x;
    if (i >= n4) return;
    float4 v = in[i];
    H4 h;
    h.a = __floats2half2_rn(v.x, v.y);
    h.b = __floats2half2_rn(v.z, v.w);
    out[i] = h;
}

// =================== fp16 cp.async GEMM ====================================
// CTA 128x128, BK=64 halves, 8 warps (2x4), warp tile 64x32, 3 smem stages.
#define HSTG_BY   32768
#define GEMM_SMEM (3 * HSTG_BY)

__device__ __forceinline__ void issue_chunk_h(uint32_t sdst,
                                              const __half* __restrict__ A,
                                              const __half* __restrict__ W,
                                              int row0, int col0, int kb, int tid)
{
#pragma unroll
    for (int i = 0; i < 4; i++) {
        int f = tid + i * 256;
        int row = f >> 3, c = f & 7;
        uint32_t doff = (uint32_t)(row * 128 + ((c ^ (row & 7)) * 16));
        cp16(sdst + doff,         A + (size_t)(row0 + row) * D_ + kb + c * 8);
        cp16(sdst + 16384 + doff, W + (size_t)(col0 + row) * D_ + kb + c * 8);
    }
    CP_COMMIT();
}

__device__ __forceinline__ void compute_chunk_h(uint32_t sbase,
                                                int wm, int wn, int lane,
                                                float acc[4][4][4])
{
    const uint32_t Ab = sbase;
    const uint32_t Bb = sbase + 16384;
    const int g  = lane >> 3;
    const int l8 = lane & 7;
#pragma unroll
    for (int ks = 0; ks < 4; ks++) {
        uint32_t afr[4][4], bfr[4][2];
#pragma unroll
        for (int mb = 0; mb < 4; mb++) {
            const int r = wm * 64 + mb * 16 + ((g & 1) << 3) + l8;
            const int u = 2 * ks + (g >> 1);
            ldsm_x4(afr[mb], Ab + r * 128 + ((u ^ (r & 7)) * 16));
        }
#pragma unroll
        for (int nb = 0; nb < 4; nb++) {
            const int r = wn * 32 + nb * 8 + l8;
            const int u = 2 * ks + ((lane >> 3) & 1);
            ldsm_x2(bfr[nb], Bb + r * 128 + ((u ^ (r & 7)) * 16));
        }
#pragma unroll
        for (int mb = 0; mb < 4; mb++)
#pragma unroll
            for (int nb = 0; nb < 4; nb++)
                mma_f16(acc[mb][nb], afr[mb], bfr[nb]);
    }
}

// FUSED=1: z in {0,1,2}; z<2 writes fp32 C, z==2 writes fp16 V transposed.
template <int FUSED>
__global__ __launch_bounds__(256, 2)
void gemm_f16(const __half* __restrict__ A,
              const __half* __restrict__ W0, const __half* __restrict__ W1,
              const __half* __restrict__ W2,
              const float* __restrict__ b0, const float* __restrict__ b1,
              const float* __restrict__ b2,
              float* __restrict__ C0, float* __restrict__ C1,
              __half* __restrict__ CV)
{
    extern __shared__ char dsm[];
    const uint32_t s_u32 = smem_u32(dsm);

    const int z = FUSED ? blockIdx.z : 0;
    const __half* W    = (z == 0) ? W0 : (z == 1) ? W1 : W2;
    const float*  bias = (z == 0) ? b0 : (z == 1) ? b1 : b2;
    float*        C    = (z == 0) ? C0 : C1;

    const int tid  = threadIdx.x;
    const int wid  = tid >> 5;
    const int lane = tid & 31;
    const int wm   = wid >> 2;
    const int wn   = wid & 3;
    const int lq   = lane >> 2;
    const int lr   = lane & 3;
    const int row0 = blockIdx.y << 7;
    const int col0 = blockIdx.x << 7;

    float acc[4][4][4];
#pragma unroll
    for (int i = 0; i < 4; i++)
#pragma unroll
        for (int j = 0; j < 4; j++)
#pragma unroll
            for (int r = 0; r < 4; r++) acc[i][j][r] = 0.f;

    const int NCH = D_ / 64;   // 32

    issue_chunk_h(s_u32,           A, W, row0, col0, 0,  tid);
    issue_chunk_h(s_u32 + HSTG_BY, A, W, row0, col0, 64, tid);

    for (int ch = 0; ch < NCH - 2; ch++) {
        issue_chunk_h(s_u32 + ((ch + 2) % 3) * HSTG_BY, A, W, row0, col0,
                      (ch + 2) * 64, tid);
        CP_WAIT(2);
        __syncthreads();
        compute_chunk_h(s_u32 + (ch % 3) * HSTG_BY, wm, wn, lane, acc);
        __syncthreads();
    }
    CP_WAIT(1);
    __syncthreads();
    compute_chunk_h(s_u32 + ((NCH - 2) % 3) * HSTG_BY, wm, wn, lane, acc);
    __syncthreads();
    CP_WAIT(0);
    __syncthreads();
    compute_chunk_h(s_u32 + ((NCH - 1) % 3) * HSTG_BY, wm, wn, lane, acc);

    if (FUSED && z == 2) {
        const int bidx = row0 >> 11;
        const size_t vbase = ((size_t)bidx * 16 + blockIdx.x) * ((size_t)DH_ * S_);
#pragma unroll
        for (int mb = 0; mb < 4; mb++) {
#pragma unroll
            for (int nb = 0; nb < 4; nb++) {
                const int col = wn * 32 + nb * 8 + lr * 2;
                const float2 bv = *(const float2*)(bias + col0 + col);
                const int r0 = row0 + wm * 64 + mb * 16 + lq;
                const int s0 = r0 & (S_ - 1);
                CV[vbase + (size_t)(col    ) * S_ + s0]     = __float2half_rn(acc[mb][nb][0] + bv.x);
                CV[vbase + (size_t)(col + 1) * S_ + s0]     = __float2half_rn(acc[mb][nb][1] + bv.y);
                CV[vbase + (size_t)(col    ) * S_ + s0 + 8] = __float2half_rn(acc[mb][nb][2] + bv.x);
                CV[vbase + (size_t)(col + 1) * S_ + s0 + 8] = __float2half_rn(acc[mb][nb][3] + bv.y);
            }
        }
    } else {
#pragma unroll
        for (int mb = 0; mb < 4; mb++) {
#pragma unroll
            for (int nb = 0; nb < 4; nb++) {
                const int col = col0 + wn * 32 + nb * 8 + lr * 2;
                const float2 bv = *(const float2*)(bias + col);
                const int r0 = row0 + wm * 64 + mb * 16 + lq;
                float2 o0, o1;
                o0.x = acc[mb][nb][0] + bv.x;
                o0.y = acc[mb][nb][1] + bv.y;
                o1.x = acc[mb][nb][2] + bv.x;
                o1.y = acc[mb][nb][3] + bv.y;
                *(float2*)(C + (size_t)r0 * D_ + col)       = o0;
                *(float2*)(C + (size_t)(r0 + 8) * D_ + col) = o1;
            }
        }
    }
}

// ---------------- RoPE: fp32 in, fp16 out; Q pre-scaled by 1/sqrt(Dh) ------
__global__ void rope_kernel(const float* __restrict__ q, const float* __restrict__ k,
                            __half* __restrict__ qh, __half* __restrict__ kh)
{
    int idx = blockIdx.x * blockDim.x + threadIdx.x;
    int d0 = idx & 63;
    int h  = (idx >> 6) & (H_ - 1);
    int s  = (idx >> 10) & (S_ - 1);
    int b  = idx >> 21;

    float inv = exp2f(-(float)d0 * (13.287712379549449f / 64.f));
    float ang = (float)s * inv;
    float sn, cs;
    sincosf(ang, &sn, &cs);

    const float scale = 0.08838834764831845f;  // 1/sqrt(128)
    size_t base = ((size_t)(b * S_ + s) * D_) + (size_t)h * DH_ + d0;

    float q1 = q[base], q2 = q[base + 64];
    qh[base]      = __float2half_rn((q1 * cs - q2 * sn) * scale);
    qh[base + 64] = __float2half_rn((q2 * cs + q1 * sn) * scale);

    float k1 = k[base], k2 = k[base + 64];
    kh[base]      = __float2half_rn(k1 * cs - k2 * sn);
    kh[base + 64] = __float2half_rn(k2 * cs + k1 * sn);
}

// ---------------- Flash attention (fp16 mma, register softmax) -------------
// Bq = Bk = 64, Dh = 128, 256 threads = 8 warps: (wm 0..3) x (wn 0..1).
#define FQH_ST 136
#define FKH_ST 136
#define FVH_ST 72
#define FPS_ST 72
#define Q_BY   (64 * FQH_ST * 2)          // 17408
#define K_BY   (64 * FKH_ST * 2)          // 17408
#define V_BY   (128 * FVH_ST * 2)         // 18432
#define KV_BY  (K_BY + V_BY)              // 35840
#define PS_BY  (64 * FPS_ST * 2)          // 9216
#define RED_BY ((128 + 128 + 64 + 64) * 4)
#define FLASH_BYTES (Q_BY + 2 * KV_BY + PS_BY + RED_BY)

__global__ __launch_bounds__(256)
void flash_h(const __half* __restrict__ qh, const __half* __restrict__ kh,
             const __half* __restrict__ vh, __half* __restrict__ o)
{
    extern __shared__ char fsm[];
    const uint32_t Qs  = smem_u32(fsm);
    const uint32_t KV0 = Qs + Q_BY;
    const uint32_t Psm = KV0 + 2 * KV_BY;
    float* redmax = (float*)(fsm + Q_BY + 2 * KV_BY + PS_BY);  // [2][64]
    float* redsum = redmax + 128;                               // [2][64]
    float* row_m  = redsum + 128;                               // [64]
    float* row_l  = row_m + 64;                                 // [64]
    __half* Ps    = (__half*)(fsm + Q_BY + 2 * KV_BY);

    const int tid  = threadIdx.x;
    const int wid  = tid >> 5;
    const int lane = tid & 31;
    const int lq   = lane >> 2;
    const int lr   = lane & 3;
    const int g    = lane >> 3;
    const int l8   = lane & 7;
    const int wm   = wid & 3;     // 0..3
    const int wn   = wid >> 2;    // 0..1
    const int q0   = blockIdx.x * 64;
    const int bh   = blockIdx.y;
    const int b    = bh >> 4, h = bh & 15;
    const size_t head  = (size_t)b * S_ * D_ + (size_t)h * DH_;
    const size_t vhead = (size_t)bh * ((size_t)DH_ * S_);
    const int NT = S_ / 64;
    const int r0 = wm * 16 + lq;   // this thread's first row

    // ---- issue Q (group), then K/V stage 0 (group)
#pragma unroll
    for (int i = 0; i < 4; i++) {
        int f = tid + i * 256;
        int r = f >> 4, c = f & 15;
        cp16(Qs + r * (FQH_ST * 2) + c * 16,
             qh + head + (size_t)(q0 + r) * D_ + c * 8);
    }
    CP_COMMIT();
#pragma unroll
    for (int i = 0; i < 4; i++) {
        int f = tid + i * 256;
        int r = f >> 4, c = f & 15;
        cp16(KV0 + r * (FKH_ST * 2) + c * 16,
             kh + head + (size_t)r * D_ + c * 8);
    }
#pragma unroll
    for (int i = 0; i < 4; i++) {
        int f = tid + i * 256;
        int r = f >> 3, c = f & 7;
        cp16(KV0 + K_BY + r * (FVH_ST * 2) + c * 16,
             vh + vhead + (size_t)r * S_ + c * 8);
    }
    CP_COMMIT();

    if (tid < 64) { row_m[tid] = -1e30f; row_l[tid] = 0.f; }

    float oacc[8][4];
#pragma unroll
    for (int i = 0; i < 8; i++)
#pragma unroll
        for (int j = 0; j < 4; j++) oacc[i][j] = 0.f;

    CP_WAIT(0);
    __syncthreads();

    // ---- hoist Q fragments (8 k-steps x 4 regs)
    uint32_t qfr[8][4];
#pragma unroll
    for (int ks = 0; ks < 8; ks++) {
        const int r = wm * 16 + ((g & 1) << 3) + l8;
        ldsm_x4(qfr[ks], Qs + (r * FQH_ST + ks * 16 + (g >> 1) * 8) * 2);
    }

    for (int kt = 0; kt < NT; kt++) {
        const uint32_t KVc = KV0 + (kt & 1) * KV_BY;
        // ---- prefetch next K/V stage
        if (kt + 1 < NT) {
            const uint32_t KVn = KV0 + ((kt + 1) & 1) * KV_BY;
            const int kg = (kt + 1) * 64;
#pragma unroll
            for (int i = 0; i < 4; i++) {
                int f = tid + i * 256;
                int r = f >> 4, c = f & 15;
                cp16(KVn + r * (FKH_ST * 2) + c * 16,
                     kh + head + (size_t)(kg + r) * D_ + c * 8);
            }
#pragma unroll
            for (int i = 0; i < 4; i++) {
                int f = tid + i * 256;
                int r = f >> 3, c = f & 7;
                cp16(KVn + K_BY + r * (FVH_ST * 2) + c * 16,
                     vh + vhead + (size_t)r * S_ + kg + c * 8);
            }
            CP_COMMIT();
            if (kt > 0) CP_WAIT(1);
        } else {
            CP_WAIT(0);
        }
        __syncthreads();

        // ---- S = Q K^T (warp tile 16x32, m16n8k16; Q pre-scaled)
        float sacc[4][4];
#pragma unroll
        for (int i = 0; i < 4; i++)
#pragma unroll
            for (int j = 0; j < 4; j++) sacc[i][j] = 0.f;

#pragma unroll
        for (int ks = 0; ks < 8; ks++) {
            uint32_t bq[4][2];
#pragma unroll
            for (int nb = 0; nb < 4; nb++) {
                const int n = wn * 32 + nb * 8 + l8;
                ldsm_x2(bq[nb], KVc + (n * FKH_ST + ks * 16 + ((lane >> 3) & 1) * 8) * 2);
            }
#pragma unroll
            for (int nb = 0; nb < 4; nb++) mma_f16(sacc[nb], qfr[ks], bq[nb]);
        }

        // ---- phase A: per-warp row max (shfl over lr-group of 4 lanes)
        float m0 = -1e30f, m1 = -1e30f;
#pragma unroll
        for (int nb = 0; nb < 4; nb++) {
            m0 = fmaxf(m0, fmaxf(sacc[nb][0], sacc[nb][1]));
            m1 = fmaxf(m1, fmaxf(sacc[nb][2], sacc[nb][3]));
        }
        m0 = fmaxf(m0, __shfl_xor_sync(0xffffffffu, m0, 1));
        m0 = fmaxf(m0, __shfl_xor_sync(0xffffffffu, m0, 2));
        m1 = fmaxf(m1, __shfl_xor_sync(0xffffffffu, m1, 1));
        m1 = fmaxf(m1, __shfl_xor_sync(0xffffffffu, m1, 2));
        if (lr == 0) {
            redmax[wn * 64 + r0]     = m0;
            redmax[wn * 64 + r0 + 8] = m1;
        }
        __syncthreads();

        // ---- phase B: combine maxes, exp in registers, write fp16 P
        const float mo0 = row_m[r0], mo1 = row_m[r0 + 8];
        const float mn0 = fmaxf(mo0, fmaxf(redmax[r0],     redmax[64 + r0]));
        const float mn1 = fmaxf(mo1, fmaxf(redmax[r0 + 8], redmax[64 + r0 + 8]));
        const float al0 = __expf(mo0 - mn0);
        const float al1 = __expf(mo1 - mn1);
        float s0 = 0.f, s1 = 0.f;
#pragma unroll
        for (int nb = 0; nb < 4; nb++) {
            const int col = wn * 32 + nb * 8 + 2 * lr;
            float p0 = __expf(sacc[nb][0] - mn0);
            float p1 = __expf(sacc[nb][1] - mn0);
            float p2 = __expf(sacc[nb][2] - mn1);
            float p3 = __expf(sacc[nb][3] - mn1);
            s0 += p0 + p1;
            s1 += p2 + p3;
            *(__half2*)(Ps + (r0    ) * FPS_ST + col) = __floats2half2_rn(p0, p1);
            *(__half2*)(Ps + (r0 + 8) * FPS_ST + col) = __floats2half2_rn(p2, p3);
        }
        s0 += __shfl_xor_sync(0xffffffffu, s0, 1);
        s0 += __shfl_xor_sync(0xffffffffu, s0, 2);
        s1 += __shfl_xor_sync(0xffffffffu, s1, 1);
        s1 += __shfl_xor_sync(0xffffffffu, s1, 2);
        if (lr == 0) {
            redsum[wn * 64 + r0]     = s0;
            redsum[wn * 64 + r0 + 8] = s1;
        }
        // rescale O accumulators
#pragma unroll
        for (int nb = 0; nb < 8; nb++) {
            oacc[nb][0] *= al0; oacc[nb][1] *= al0;
            oacc[nb][2] *= al1; oacc[nb][3] *= al1;
        }
        __syncthreads();

        // ---- phase C: designated thread updates running (m, l)
        if (wn == 0 && lr == 0) {
            row_l[r0]     = row_l[r0]     * al0 + redsum[r0]     + redsum[64 + r0];
            row_m[r0]     = mn0;
            row_l[r0 + 8] = row_l[r0 + 8] * al1 + redsum[r0 + 8] + redsum[64 + r0 + 8];
            row_m[r0 + 8] = mn1;
        }

        // ---- O += P V (warp tile 16x64, m16n8k16)
#pragma unroll
        for (int ks = 0; ks < 4; ks++) {
            uint32_t a[4], bv[8][2];
            const int ar = wm * 16 + ((g & 1) << 3) + l8;
            ldsm_x4(a, Psm + (ar * FPS_ST + ks * 16 + (g >> 1) * 8) * 2);
#pragma unroll
            for (int nb = 0; nb < 8; nb++) {
                const int n = wn * 64 + nb * 8 + l8;
                ldsm_x2(bv[nb], KVc + K_BY + (n * FVH_ST + ks * 16 + ((lane >> 3) & 1) * 8) * 2);
            }
#pragma unroll
            for (int nb = 0; nb < 8; nb++) mma_f16(oacc[nb], a, bv[nb]);
        }
        __syncthreads();
    }

    // ---- epilogue: normalize, write fp16 att
    const float il0 = 1.f / row_l[r0];
    const float il1 = 1.f / row_l[r0 + 8];
#pragma unroll
    for (int nb = 0; nb < 8; nb++) {
        const int col = wn * 64 + nb * 8 + 2 * lr;
        const int r   = q0 + r0;
        *(__half2*)(o + head + (size_t)r * D_ + col) =
            __floats2half2_rn(oacc[nb][0] * il0, oacc[nb][1] * il0);
        *(__half2*)(o + head + (size_t)(r + 8) * D_ + col) =
            __floats2half2_rn(oacc[nb][2] * il1, oacc[nb][3] * il1);
    }
}

// ---------------- launch ---------------------------------------------------
extern "C" void kernel_launch(void* const* d_in, const int* in_sizes, int n_in,
                              void* d_out, int out_size)
{
    const float* x   = (const float*)d_in[0];
    const float* q_w = (const float*)d_in[1];
    const float* k_w = (const float*)d_in[2];
    const float* v_w = (const float*)d_in[3];
    const float* q_b = (const float*)d_in[4];
    const float* k_b = (const float*)d_in[5];
    const float* v_b = (const float*)d_in[6];
    const float* o_w = (const float*)d_in[7];
    const float* o_b = (const float*)d_in[8];
    float* out = (float*)d_out;

    float  *qp, *kp;
    __half *qhp, *khp, *vhp, *xh, *wqh, *wkh, *wvh, *woh, *ath;
    cudaGetSymbolAddress((void**)&qp,  g_q);
    cudaGetSymbolAddress((void**)&kp,  g_k);
    cudaGetSymbolAddress((void**)&qhp, g_qh);
    cudaGetSymbolAddress((void**)&khp, g_kh);
    cudaGetSymbolAddress((void**)&vhp, g_vh);
    cudaGetSymbolAddress((void**)&xh,  g_xh);
    cudaGetSymbolAddress((void**)&wqh, g_wqh);
    cudaGetSymbolAddress((void**)&wkh, g_wkh);
    cudaGetSymbolAddress((void**)&wvh, g_wvh);
    cudaGetSymbolAddress((void**)&woh, g_woh);
    cudaGetSymbolAddress((void**)&ath, g_atth);

    cudaFuncSetAttribute(flash_h,
                         cudaFuncAttributeMaxDynamicSharedMemorySize, FLASH_BYTES);
    cudaFuncSetAttribute(gemm_f16<1>,
                         cudaFuncAttributeMaxDynamicSharedMemorySize, GEMM_SMEM);
    cudaFuncSetAttribute(gemm_f16<0>,
                         cudaFuncAttributeMaxDynamicSharedMemorySize, GEMM_SMEM);

    // fp32 -> fp16 conversions
    const int n4x = (M_ * D_) / 4;
    const int n4w = (D_ * D_) / 4;
    f32to16_kernel<<<n4x / 256, 256>>>((const float4*)x,   (H4*)xh,  n4x);
    f32to16_kernel<<<n4w / 256, 256>>>((const float4*)q_w, (H4*)wqh, n4w);
    f32to16_kernel<<<n4w / 256, 256>>>((const float4*)k_w, (H4*)wkh, n4w);
    f32to16_kernel<<<n4w / 256, 256>>>((const float4*)v_w, (H4*)wvh, n4w);
    f32to16_kernel<<<n4w / 256, 256>>>((const float4*)o_w, (H4*)woh, n4w);

    // fused QKV projections (z = 0:Q fp32, 1:K fp32, 2:V fp16 transposed)
    gemm_f16<1><<<dim3(D_ / 128, M_ / 128, 3), 256, GEMM_SMEM>>>(
        xh, wqh, wkh, wvh, q_b, k_b, v_b, qp, kp, vhp);

    rope_kernel<<<(B_ * S_ * H_ * 64) / 256, 256>>>(qp, kp, qhp, khp);

    flash_h<<<dim3(S_ / 64, B_ * H_), 256, FLASH_BYTES>>>(qhp, khp, vhp, ath);

    // output projection (fp16 att input, fp32 out)
    gemm_f16<0><<<dim3(D_ / 128, M_ / 128, 1), 256, GEMM_SMEM>>>(
        ath, woh, woh, woh, o_b, o_b, o_b, out, out, (__half*)nullptr);
}

// round 11
// speedup vs baseline: 9.5915x; 1.0113x over previous
#include <cuda_runtime.h>
#include <cuda_fp16.h>
#include <cstdint>

#define B_  2
#define S_  2048
#define D_  2048
#define H_  16
#define DH_ 128
#define M_  (B_ * S_)   // 4096

// ---------------- scratch (device globals; no allocation allowed) ----------
__device__ __half g_qh[(size_t)M_ * D_];   // fp16 Q (rope'd, pre-scaled)
__device__ __half g_kh[(size_t)M_ * D_];   // fp16 K (rope'd)
__device__ __half g_vh[(size_t)M_ * D_];   // fp16 V TRANSPOSED [(b*16+h)][d][s]
__device__ __half g_xh[(size_t)M_ * D_];   // fp16 x
__device__ __half g_wqh[(size_t)D_ * D_];
__device__ __half g_wkh[(size_t)D_ * D_];
__device__ __half g_wvh[(size_t)D_ * D_];
__device__ __half g_woh[(size_t)D_ * D_];
__device__ __half g_atth[(size_t)M_ * D_]; // fp16 attention output

// =================== helpers ===============================================
__device__ __forceinline__ void mma_f16(float* d,
                                        const uint32_t* a,
                                        const uint32_t* b) {
    asm volatile(
        "mma.sync.aligned.m16n8k16.row.col.f32.f16.f16.f32 "
        "{%0,%1,%2,%3}, {%4,%5,%6,%7}, {%8,%9}, {%0,%1,%2,%3};"
        : "+f"(d[0]), "+f"(d[1]), "+f"(d[2]), "+f"(d[3])
        : "r"(a[0]), "r"(a[1]), "r"(a[2]), "r"(a[3]),
          "r"(b[0]), "r"(b[1]));
}

__device__ __forceinline__ void ldsm_x4(uint32_t* r, uint32_t addr) {
    asm volatile("ldmatrix.sync.aligned.m8n8.x4.shared.b16 {%0,%1,%2,%3}, [%4];"
                 : "=r"(r[0]), "=r"(r[1]), "=r"(r[2]), "=r"(r[3]) : "r"(addr));
}
__device__ __forceinline__ void ldsm_x2(uint32_t* r, uint32_t addr) {
    asm volatile("ldmatrix.sync.aligned.m8n8.x2.shared.b16 {%0,%1}, [%2];"
                 : "=r"(r[0]), "=r"(r[1]) : "r"(addr));
}

__device__ __forceinline__ void cp16(uint32_t dst, const void* src) {
    asm volatile("cp.async.cg.shared.global [%0], [%1], 16;" :: "r"(dst), "l"(src));
}
#define CP_COMMIT() asm volatile("cp.async.commit_group;" ::: "memory")
#define CP_WAIT(n)  asm volatile("cp.async.wait_group %0;" :: "n"(n) : "memory")

__device__ __forceinline__ uint32_t smem_u32(const void* p) {
    uint32_t a;
    asm("{ .reg .u64 t; cvta.to.shared.u64 t, %1; cvt.u32.u64 %0, t; }"
        : "=r"(a) : "l"(p));
    return a;
}

// ---------------- fused fp32 -> fp16 conversion (x + 4 weights) ------------
struct alignas(8) H4 { __half2 a, b; };
#define XN4 (M_ * D_ / 4)   // 2^21
#define WN4 (D_ * D_ / 4)   // 2^20
__global__ void conv_all(const float4* __restrict__ x,
                         const float4* __restrict__ w0, const float4* __restrict__ w1,
                         const float4* __restrict__ w2, const float4* __restrict__ w3,
                         H4* __restrict__ xo,
                         H4* __restrict__ o0, H4* __restrict__ o1,
                         H4* __restrict__ o2, H4* __restrict__ o3)
{
    int i = blockIdx.x * blockDim.x + threadIdx.x;   // 0 .. 6*2^20-1
    const float4* src; H4* dst; int off;
    if (i < XN4) { src = x; dst = xo; off = i; }
    else {
        int j = i - XN4;
        int r = j >> 20;
        off = j & (WN4 - 1);
        src = (r == 0) ? w0 : (r == 1) ? w1 : (r == 2) ? w2 : w3;
        dst = (r == 0) ? o0 : (r == 1) ? o1 : (r == 2) ? o2 : o3;
    }
    float4 v = src[off];
    H4 h;
    h.a = __floats2half2_rn(v.x, v.y);
    h.b = __floats2half2_rn(v.z, v.w);
    dst[off] = h;
}

// =================== fp16 cp.async GEMM ====================================
// CTA 128x128, BK=64 halves, 8 warps (2x4), warp tile 64x32, 3 smem stages.
// Warp n-columns remapped: col(nb) = wn*16 + (nb&1)*8 + (nb>>1)*64  (+2*lr)
// so each thread holds both rope partners (d, d+64) in registers.
#define HSTG_BY   32768
#define GEMM_SMEM (3 * HSTG_BY)

__device__ __forceinline__ void issue_chunk_h(uint32_t sdst,
                                              const __half* __restrict__ A,
                                              const __half* __restrict__ W,
                                              int row0, int col0, int kb, int tid)
{
#pragma unroll
    for (int i = 0; i < 4; i++) {
        int f = tid + i * 256;
        int row = f >> 3, c = f & 7;
        uint32_t doff = (uint32_t)(row * 128 + ((c ^ (row & 7)) * 16));
        cp16(sdst + doff,         A + (size_t)(row0 + row) * D_ + kb + c * 8);
        cp16(sdst + 16384 + doff, W + (size_t)(col0 + row) * D_ + kb + c * 8);
    }
    CP_COMMIT();
}

__device__ __forceinline__ void compute_chunk_h(uint32_t sbase,
                                                int wm, int wn, int lane,
                                                float acc[4][4][4])
{
    const uint32_t Ab = sbase;
    const uint32_t Bb = sbase + 16384;
    const int g  = lane >> 3;
    const int l8 = lane & 7;
#pragma unroll
    for (int ks = 0; ks < 4; ks++) {
        uint32_t afr[4][4], bfr[4][2];
#pragma unroll
        for (int mb = 0; mb < 4; mb++) {
            const int r = wm * 64 + mb * 16 + ((g & 1) << 3) + l8;
            const int u = 2 * ks + (g >> 1);
            ldsm_x4(afr[mb], Ab + r * 128 + ((u ^ (r & 7)) * 16));
        }
#pragma unroll
        for (int nb = 0; nb < 4; nb++) {
            const int r = wn * 16 + (nb & 1) * 8 + (nb >> 1) * 64 + l8;
            const int u = 2 * ks + ((lane >> 3) & 1);
            ldsm_x2(bfr[nb], Bb + r * 128 + ((u ^ (r & 7)) * 16));
        }
#pragma unroll
        for (int mb = 0; mb < 4; mb++)
#pragma unroll
            for (int nb = 0; nb < 4; nb++)
                mma_f16(acc[mb][nb], afr[mb], bfr[nb]);
    }
}

// FUSED=1: z=0 -> fp16 rope'd+scaled Q; z=1 -> fp16 rope'd K; z=2 -> fp16 V^T.
// FUSED=0: fp32 C with bias (output projection).
template <int FUSED>
__global__ __launch_bounds__(256, 2)
void gemm_f16(const __half* __restrict__ A,
              const __half* __restrict__ W0, const __half* __restrict__ W1,
              const __half* __restrict__ W2,
              const float* __restrict__ b0, const float* __restrict__ b1,
              const float* __restrict__ b2,
              float* __restrict__ C0,
              __half* __restrict__ CQ, __half* __restrict__ CK,
              __half* __restrict__ CV)
{
    extern __shared__ char dsm[];
    const uint32_t s_u32 = smem_u32(dsm);

    const int z = FUSED ? blockIdx.z : 0;
    const __half* W    = (z == 0) ? W0 : (z == 1) ? W1 : W2;
    const float*  bias = (z == 0) ? b0 : (z == 1) ? b1 : b2;

    const int tid  = threadIdx.x;
    const int wid  = tid >> 5;
    const int lane = tid & 31;
    const int wm   = wid >> 2;
    const int wn   = wid & 3;
    const int lq   = lane >> 2;
    const int lr   = lane & 3;
    const int row0 = blockIdx.y << 7;
    const int col0 = blockIdx.x << 7;

    float acc[4][4][4];
#pragma unroll
    for (int i = 0; i < 4; i++)
#pragma unroll
        for (int j = 0; j < 4; j++)
#pragma unroll
            for (int r = 0; r < 4; r++) acc[i][j][r] = 0.f;

    const int NCH = D_ / 64;   // 32

    issue_chunk_h(s_u32,           A, W, row0, col0, 0,  tid);
    issue_chunk_h(s_u32 + HSTG_BY, A, W, row0, col0, 64, tid);

    // single-sync mainloop: wait -> sync -> issue -> compute
    for (int ch = 0; ch < NCH; ch++) {
        if (ch < NCH - 1) { CP_WAIT(1); } else { CP_WAIT(0); }
        __syncthreads();
        if (ch + 2 < NCH)
            issue_chunk_h(s_u32 + ((ch + 2) % 3) * HSTG_BY, A, W, row0, col0,
                          (ch + 2) * 64, tid);
        compute_chunk_h(s_u32 + (ch % 3) * HSTG_BY, wm, wn, lane, acc);
    }

    if (!FUSED) {
        // fp32 epilogue with bias (out projection)
#pragma unroll
        for (int mb = 0; mb < 4; mb++) {
#pragma unroll
            for (int nb = 0; nb < 4; nb++) {
                const int col = col0 + wn * 16 + (nb & 1) * 8 + (nb >> 1) * 64 + lr * 2;
                const float2 bv = *(const float2*)(bias + col);
                const int r0 = row0 + wm * 64 + mb * 16 + lq;
                float2 o0, o1;
                o0.x = acc[mb][nb][0] + bv.x;
                o0.y = acc[mb][nb][1] + bv.y;
                o1.x = acc[mb][nb][2] + bv.x;
                o1.y = acc[mb][nb][3] + bv.y;
                *(float2*)(C0 + (size_t)r0 * D_ + col)       = o0;
                *(float2*)(C0 + (size_t)(r0 + 8) * D_ + col) = o1;
            }
        }
    } else if (z == 2) {
        // fp16 V transposed epilogue: out[(b*16+h)][d][s], h = blockIdx.x
        const int bidx = row0 >> 11;
        const size_t vbase = ((size_t)bidx * 16 + blockIdx.x) * ((size_t)DH_ * S_);
#pragma unroll
        for (int mb = 0; mb < 4; mb++) {
#pragma unroll
            for (int nb = 0; nb < 4; nb++) {
                const int col = wn * 16 + (nb & 1) * 8 + (nb >> 1) * 64 + lr * 2;
                const float2 bv = *(const float2*)(bias + col0 + col);
                const int r0 = row0 + wm * 64 + mb * 16 + lq;
                const int s0 = r0 & (S_ - 1);
                CV[vbase + (size_t)(col    ) * S_ + s0]     = __float2half_rn(acc[mb][nb][0] + bv.x);
                CV[vbase + (size_t)(col + 1) * S_ + s0]     = __float2half_rn(acc[mb][nb][1] + bv.y);
                CV[vbase + (size_t)(col    ) * S_ + s0 + 8] = __float2half_rn(acc[mb][nb][2] + bv.x);
                CV[vbase + (size_t)(col + 1) * S_ + s0 + 8] = __float2half_rn(acc[mb][nb][3] + bv.y);
            }
        }
    } else {
        // fp16 rope epilogue (Q: scaled by 1/sqrt(Dh); K: unscaled)
        const float qs = (z == 0) ? 0.08838834764831845f : 1.0f;
        __half* Ch = (z == 0) ? CQ : CK;
        const float cexp = 13.287712379549449f / 64.f;   // log2(10000)/64
#pragma unroll
        for (int nbp = 0; nbp < 2; nbp++) {
            const int dcol = wn * 16 + nbp * 8 + 2 * lr;          // 0..62
            const float inv0 = exp2f(-(float)dcol * cexp);
            const float inv1 = exp2f(-(float)(dcol + 1) * cexp);
            const float2 bv  = *(const float2*)(bias + col0 + dcol);
            const float2 bv2 = *(const float2*)(bias + col0 + dcol + 64);
#pragma unroll
            for (int mb = 0; mb < 4; mb++) {
#pragma unroll
                for (int hf = 0; hf < 2; hf++) {
                    const int r = row0 + wm * 64 + mb * 16 + lq + hf * 8;
                    const float s = (float)(r & (S_ - 1));
                    float sn0, cs0, sn1, cs1;
                    sincosf(s * inv0, &sn0, &cs0);
                    sincosf(s * inv1, &sn1, &cs1);
                    const float v0 = acc[mb][nbp    ][hf * 2 + 0] + bv.x;   // d
                    const float v1 = acc[mb][nbp    ][hf * 2 + 1] + bv.y;   // d+1
                    const float p0 = acc[mb][nbp + 2][hf * 2 + 0] + bv2.x;  // d+64
                    const float p1 = acc[mb][nbp + 2][hf * 2 + 1] + bv2.y;  // d+65
                    *(__half2*)(Ch + (size_t)r * D_ + col0 + dcol) =
                        __floats2half2_rn((v0 * cs0 - p0 * sn0) * qs,
                                          (v1 * cs1 - p1 * sn1) * qs);
                    *(__half2*)(Ch + (size_t)r * D_ + col0 + dcol + 64) =
                        __floats2half2_rn((p0 * cs0 + v0 * sn0) * qs,
                                          (p1 * cs1 + v1 * sn1) * qs);
                }
            }
        }
    }
}

// ---------------- Flash attention (fp16 mma, register softmax) -------------
// Bq = Bk = 64, Dh = 128, 256 threads = 8 warps: (wm 0..3) x (wn 0..1).
#define FQH_ST 136
#define FKH_ST 136
#define FVH_ST 72
#define FPS_ST 72
#define Q_BY   (64 * FQH_ST * 2)          // 17408
#define K_BY   (64 * FKH_ST * 2)          // 17408
#define V_BY   (128 * FVH_ST * 2)         // 18432
#define KV_BY  (K_BY + V_BY)              // 35840
#define PS_BY  (64 * FPS_ST * 2)          // 9216
#define RED_BY ((128 + 128 + 64 + 64) * 4)
#define FLASH_BYTES (Q_BY + 2 * KV_BY + PS_BY + RED_BY)

__global__ __launch_bounds__(256)
void flash_h(const __half* __restrict__ qh, const __half* __restrict__ kh,
             const __half* __restrict__ vh, __half* __restrict__ o)
{
    extern __shared__ char fsm[];
    const uint32_t Qs  = smem_u32(fsm);
    const uint32_t KV0 = Qs + Q_BY;
    const uint32_t Psm = KV0 + 2 * KV_BY;
    float* redmax = (float*)(fsm + Q_BY + 2 * KV_BY + PS_BY);  // [2][64]
    float* redsum = redmax + 128;                               // [2][64]
    float* row_m  = redsum + 128;                               // [64]
    float* row_l  = row_m + 64;                                 // [64]
    __half* Ps    = (__half*)(fsm + Q_BY + 2 * KV_BY);

    const int tid  = threadIdx.x;
    const int wid  = tid >> 5;
    const int lane = tid & 31;
    const int lq   = lane >> 2;
    const int lr   = lane & 3;
    const int g    = lane >> 3;
    const int l8   = lane & 7;
    const int wm   = wid & 3;     // 0..3
    const int wn   = wid >> 2;    // 0..1
    const int q0   = blockIdx.x * 64;
    const int bh   = blockIdx.y;
    const int b    = bh >> 4, h = bh & 15;
    const size_t head  = (size_t)b * S_ * D_ + (size_t)h * DH_;
    const size_t vhead = (size_t)bh * ((size_t)DH_ * S_);
    const int NT = S_ / 64;
    const int r0 = wm * 16 + lq;

    // ---- issue Q (group), then K/V stage 0 (group)
#pragma unroll
    for (int i = 0; i < 4; i++) {
        int f = tid + i * 256;
        int r = f >> 4, c = f & 15;
        cp16(Qs + r * (FQH_ST * 2) + c * 16,
             qh + head + (size_t)(q0 + r) * D_ + c * 8);
    }
    CP_COMMIT();
#pragma unroll
    for (int i = 0; i < 4; i++) {
        int f = tid + i * 256;
        int r = f >> 4, c = f & 15;
        cp16(KV0 + r * (FKH_ST * 2) + c * 16,
             kh + head + (size_t)r * D_ + c * 8);
    }
#pragma unroll
    for (int i = 0; i < 4; i++) {
        int f = tid + i * 256;
        int r = f >> 3, c = f & 7;
        cp16(KV0 + K_BY + r * (FVH_ST * 2) + c * 16,
             vh + vhead + (size_t)r * S_ + c * 8);
    }
    CP_COMMIT();

    if (tid < 64) { row_m[tid] = -1e30f; row_l[tid] = 0.f; }

    float oacc[8][4];
#pragma unroll
    for (int i = 0; i < 8; i++)
#pragma unroll
        for (int j = 0; j < 4; j++) oacc[i][j] = 0.f;

    CP_WAIT(0);
    __syncthreads();

    uint32_t qfr[8][4];
#pragma unroll
    for (int ks = 0; ks < 8; ks++) {
        const int r = wm * 16 + ((g & 1) << 3) + l8;
        ldsm_x4(qfr[ks], Qs + (r * FQH_ST + ks * 16 + (g >> 1) * 8) * 2);
    }

    for (int kt = 0; kt < NT; kt++) {
        const uint32_t KVc = KV0 + (kt & 1) * KV_BY;
        if (kt + 1 < NT) {
            const uint32_t KVn = KV0 + ((kt + 1) & 1) * KV_BY;
            const int kg = (kt + 1) * 64;
#pragma unroll
            for (int i = 0; i < 4; i++) {
                int f = tid + i * 256;
                int r = f >> 4, c = f & 15;
                cp16(KVn + r * (FKH_ST * 2) + c * 16,
                     kh + head + (size_t)(kg + r) * D_ + c * 8);
            }
#pragma unroll
            for (int i = 0; i < 4; i++) {
                int f = tid + i * 256;
                int r = f >> 3, c = f & 7;
                cp16(KVn + K_BY + r * (FVH_ST * 2) + c * 16,
                     vh + vhead + (size_t)r * S_ + kg + c * 8);
            }
            CP_COMMIT();
            if (kt > 0) CP_WAIT(1);
        } else {
            CP_WAIT(0);
        }
        __syncthreads();

        // ---- S = Q K^T (warp tile 16x32; Q pre-scaled)
        float sacc[4][4];
#pragma unroll
        for (int i = 0; i < 4; i++)
#pragma unroll
            for (int j = 0; j < 4; j++) sacc[i][j] = 0.f;

#pragma unroll
        for (int ks = 0; ks < 8; ks++) {
            uint32_t bq[4][2];
#pragma unroll
            for (int nb = 0; nb < 4; nb++) {
                const int n = wn * 32 + nb * 8 + l8;
                ldsm_x2(bq[nb], KVc + (n * FKH_ST + ks * 16 + ((lane >> 3) & 1) * 8) * 2);
            }
#pragma unroll
            for (int nb = 0; nb < 4; nb++) mma_f16(sacc[nb], qfr[ks], bq[nb]);
        }

        // ---- phase A: per-warp row max
        float m0 = -1e30f, m1 = -1e30f;
#pragma unroll
        for (int nb = 0; nb < 4; nb++) {
            m0 = fmaxf(m0, fmaxf(sacc[nb][0], sacc[nb][1]));
            m1 = fmaxf(m1, fmaxf(sacc[nb][2], sacc[nb][3]));
        }
        m0 = fmaxf(m0, __shfl_xor_sync(0xffffffffu, m0, 1));
        m0 = fmaxf(m0, __shfl_xor_sync(0xffffffffu, m0, 2));
        m1 = fmaxf(m1, __shfl_xor_sync(0xffffffffu, m1, 1));
        m1 = fmaxf(m1, __shfl_xor_sync(0xffffffffu, m1, 2));
        if (lr == 0) {
            redmax[wn * 64 + r0]     = m0;
            redmax[wn * 64 + r0 + 8] = m1;
        }
        __syncthreads();

        // ---- phase B: combine, exp in registers, write fp16 P
        const float mo0 = row_m[r0], mo1 = row_m[r0 + 8];
        const float mn0 = fmaxf(mo0, fmaxf(redmax[r0],     redmax[64 + r0]));
        const float mn1 = fmaxf(mo1, fmaxf(redmax[r0 + 8], redmax[64 + r0 + 8]));
        const float al0 = __expf(mo0 - mn0);
        const float al1 = __expf(mo1 - mn1);
        float s0 = 0.f, s1 = 0.f;
#pragma unroll
        for (int nb = 0; nb < 4; nb++) {
            const int col = wn * 32 + nb * 8 + 2 * lr;
            float p0 = __expf(sacc[nb][0] - mn0);
            float p1 = __expf(sacc[nb][1] - mn0);
            float p2 = __expf(sacc[nb][2] - mn1);
            float p3 = __expf(sacc[nb][3] - mn1);
            s0 += p0 + p1;
            s1 += p2 + p3;
            *(__half2*)(Ps + (r0    ) * FPS_ST + col) = __floats2half2_rn(p0, p1);
            *(__half2*)(Ps + (r0 + 8) * FPS_ST + col) = __floats2half2_rn(p2, p3);
        }
        s0 += __shfl_xor_sync(0xffffffffu, s0, 1);
        s0 += __shfl_xor_sync(0xffffffffu, s0, 2);
        s1 += __shfl_xor_sync(0xffffffffu, s1, 1);
        s1 += __shfl_xor_sync(0xffffffffu, s1, 2);
        if (lr == 0) {
            redsum[wn * 64 + r0]     = s0;
            redsum[wn * 64 + r0 + 8] = s1;
        }
#pragma unroll
        for (int nb = 0; nb < 8; nb++) {
            oacc[nb][0] *= al0; oacc[nb][1] *= al0;
            oacc[nb][2] *= al1; oacc[nb][3] *= al1;
        }
        __syncthreads();

        // ---- phase C: designated thread updates running (m, l)
        if (wn == 0 && lr == 0) {
            row_l[r0]     = row_l[r0]     * al0 + redsum[r0]     + redsum[64 + r0];
            row_m[r0]     = mn0;
            row_l[r0 + 8] = row_l[r0 + 8] * al1 + redsum[r0 + 8] + redsum[64 + r0 + 8];
            row_m[r0 + 8] = mn1;
        }

        // ---- O += P V (warp tile 16x64)
#pragma unroll
        for (int ks = 0; ks < 4; ks++) {
            uint32_t a[4], bv[8][2];
            const int ar = wm * 16 + ((g & 1) << 3) + l8;
            ldsm_x4(a, Psm + (ar * FPS_ST + ks * 16 + (g >> 1) * 8) * 2);
#pragma unroll
            for (int nb = 0; nb < 8; nb++) {
                const int n = wn * 64 + nb * 8 + l8;
                ldsm_x2(bv[nb], KVc + K_BY + (n * FVH_ST + ks * 16 + ((lane >> 3) & 1) * 8) * 2);
            }
#pragma unroll
            for (int nb = 0; nb < 8; nb++) mma_f16(oacc[nb], a, bv[nb]);
        }
        __syncthreads();
    }

    // ---- epilogue: normalize, write fp16 att
    const float il0 = 1.f / row_l[r0];
    const float il1 = 1.f / row_l[r0 + 8];
#pragma unroll
    for (int nb = 0; nb < 8; nb++) {
        const int col = wn * 64 + nb * 8 + 2 * lr;
        const int r   = q0 + r0;
        *(__half2*)(o + head + (size_t)r * D_ + col) =
            __floats2half2_rn(oacc[nb][0] * il0, oacc[nb][1] * il0);
        *(__half2*)(o + head + (size_t)(r + 8) * D_ + col) =
            __floats2half2_rn(oacc[nb][2] * il1, oacc[nb][3] * il1);
    }
}

// ---------------- launch ---------------------------------------------------
extern "C" void kernel_launch(void* const* d_in, const int* in_sizes, int n_in,
                              void* d_out, int out_size)
{
    const float* x   = (const float*)d_in[0];
    const float* q_w = (const float*)d_in[1];
    const float* k_w = (const float*)d_in[2];
    const float* v_w = (const float*)d_in[3];
    const float* q_b = (const float*)d_in[4];
    const float* k_b = (const float*)d_in[5];
    const float* v_b = (const float*)d_in[6];
    const float* o_w = (const float*)d_in[7];
    const float* o_b = (const float*)d_in[8];
    float* out = (float*)d_out;

    __half *qhp, *khp, *vhp, *xh, *wqh, *wkh, *wvh, *woh, *ath;
    cudaGetSymbolAddress((void**)&qhp, g_qh);
    cudaGetSymbolAddress((void**)&khp, g_kh);
    cudaGetSymbolAddress((void**)&vhp, g_vh);
    cudaGetSymbolAddress((void**)&xh,  g_xh);
    cudaGetSymbolAddress((void**)&wqh, g_wqh);
    cudaGetSymbolAddress((void**)&wkh, g_wkh);
    cudaGetSymbolAddress((void**)&wvh, g_wvh);
    cudaGetSymbolAddress((void**)&woh, g_woh);
    cudaGetSymbolAddress((void**)&ath, g_atth);

    cudaFuncSetAttribute(flash_h,
                         cudaFuncAttributeMaxDynamicSharedMemorySize, FLASH_BYTES);
    cudaFuncSetAttribute(gemm_f16<1>,
                         cudaFuncAttributeMaxDynamicSharedMemorySize, GEMM_SMEM);
    cudaFuncSetAttribute(gemm_f16<0>,
                         cudaFuncAttributeMaxDynamicSharedMemorySize, GEMM_SMEM);

    // fused fp32 -> fp16 conversions (x + 4 weights in one launch)
    const int total4 = XN4 + 4 * WN4;     // 6 * 2^20
    conv_all<<<total4 / 256, 256>>>(
        (const float4*)x, (const float4*)q_w, (const float4*)k_w,
        (const float4*)v_w, (const float4*)o_w,
        (H4*)xh, (H4*)wqh, (H4*)wkh, (H4*)wvh, (H4*)woh);

    // fused QKV projections with in-epilogue RoPE
    // (z = 0: Q rope'd+scaled fp16, 1: K rope'd fp16, 2: V fp16 transposed)
    gemm_f16<1><<<dim3(D_ / 128, M_ / 128, 3), 256, GEMM_SMEM>>>(
        xh, wqh, wkh, wvh, q_b, k_b, v_b,
        (float*)nullptr, qhp, khp, vhp);

    flash_h<<<dim3(S_ / 64, B_ * H_), 256, FLASH_BYTES>>>(qhp, khp, vhp, ath);

    // output projection (fp16 att input, fp32 out)
    gemm_f16<0><<<dim3(D_ / 128, M_ / 128, 1), 256, GEMM_SMEM>>>(
        ath, woh, woh, woh, o_b, o_b, o_b,
        out, (__half*)nullptr, (__half*)nullptr, (__half*)nullptr);
}

// round 12
// speedup vs baseline: 9.7526x; 1.0168x over previous
#include <cuda_runtime.h>
#include <cuda_fp16.h>
#include <cstdint>

#define B_  2
#define S_  2048
#define D_  2048
#define H_  16
#define DH_ 128
#define M_  (B_ * S_)   // 4096

// ---------------- scratch (device globals; no allocation allowed) ----------
__device__ __half g_qh[(size_t)M_ * D_];   // fp16 Q (rope'd, pre-scaled)
__device__ __half g_kh[(size_t)M_ * D_];   // fp16 K (rope'd)
__device__ __half g_vh[(size_t)M_ * D_];   // fp16 V TRANSPOSED [(b*16+h)][d][s]
__device__ __half g_xh[(size_t)M_ * D_];   // fp16 x
__device__ __half g_wqh[(size_t)D_ * D_];
__device__ __half g_wkh[(size_t)D_ * D_];
__device__ __half g_wvh[(size_t)D_ * D_];
__device__ __half g_woh[(size_t)D_ * D_];
__device__ __half g_atth[(size_t)M_ * D_]; // fp16 attention output

// =================== helpers ===============================================
__device__ __forceinline__ void mma_f16(float* d,
                                        const uint32_t* a,
                                        const uint32_t* b) {
    asm volatile(
        "mma.sync.aligned.m16n8k16.row.col.f32.f16.f16.f32 "
        "{%0,%1,%2,%3}, {%4,%5,%6,%7}, {%8,%9}, {%0,%1,%2,%3};"
        : "+f"(d[0]), "+f"(d[1]), "+f"(d[2]), "+f"(d[3])
        : "r"(a[0]), "r"(a[1]), "r"(a[2]), "r"(a[3]),
          "r"(b[0]), "r"(b[1]));
}

__device__ __forceinline__ void ldsm_x4(uint32_t* r, uint32_t addr) {
    asm volatile("ldmatrix.sync.aligned.m8n8.x4.shared.b16 {%0,%1,%2,%3}, [%4];"
                 : "=r"(r[0]), "=r"(r[1]), "=r"(r[2]), "=r"(r[3]) : "r"(addr));
}

__device__ __forceinline__ void cp16(uint32_t dst, const void* src) {
    asm volatile("cp.async.cg.shared.global [%0], [%1], 16;" :: "r"(dst), "l"(src));
}
#define CP_COMMIT() asm volatile("cp.async.commit_group;" ::: "memory")
#define CP_WAIT(n)  asm volatile("cp.async.wait_group %0;" :: "n"(n) : "memory")
#define BARPAIR(id) asm volatile("bar.sync %0, 64;" :: "r"((id) + 1) : "memory")

__device__ __forceinline__ uint32_t smem_u32(const void* p) {
    uint32_t a;
    asm("{ .reg .u64 t; cvta.to.shared.u64 t, %1; cvt.u32.u64 %0, t; }"
        : "=r"(a) : "l"(p));
    return a;
}

// ---------------- fused fp32 -> fp16 conversion (x + 4 weights) ------------
struct alignas(8) H4 { __half2 a, b; };
#define XN4 (M_ * D_ / 4)   // 2^21
#define WN4 (D_ * D_ / 4)   // 2^20
__global__ void conv_all(const float4* __restrict__ x,
                         const float4* __restrict__ w0, const float4* __restrict__ w1,
                         const float4* __restrict__ w2, const float4* __restrict__ w3,
                         H4* __restrict__ xo,
                         H4* __restrict__ o0, H4* __restrict__ o1,
                         H4* __restrict__ o2, H4* __restrict__ o3)
{
    int i = blockIdx.x * blockDim.x + threadIdx.x;
    const float4* src; H4* dst; int off;
    if (i < XN4) { src = x; dst = xo; off = i; }
    else {
        int j = i - XN4;
        int r = j >> 20;
        off = j & (WN4 - 1);
        src = (r == 0) ? w0 : (r == 1) ? w1 : (r == 2) ? w2 : w3;
        dst = (r == 0) ? o0 : (r == 1) ? o1 : (r == 2) ? o2 : o3;
    }
    float4 v = src[off];
    H4 h;
    h.a = __floats2half2_rn(v.x, v.y);
    h.b = __floats2half2_rn(v.z, v.w);
    dst[off] = h;
}

// =================== fp16 cp.async GEMM ====================================
// CTA 128x128, BK=64 halves, 8 warps (2x4), warp tile 64x32, 3 smem stages.
// Warp n-columns remapped: col(nb) = wn*16 + (nb&1)*8 + (nb>>1)*64  (+2*lr)
#define HSTG_BY   32768
#define GEMM_SMEM (3 * HSTG_BY)

__device__ __forceinline__ void issue_chunk_h(uint32_t sdst,
                                              const __half* __restrict__ A,
                                              const __half* __restrict__ W,
                                              int row0, int col0, int kb, int tid)
{
#pragma unroll
    for (int i = 0; i < 4; i++) {
        int f = tid + i * 256;
        int row = f >> 3, c = f & 7;
        uint32_t doff = (uint32_t)(row * 128 + ((c ^ (row & 7)) * 16));
        cp16(sdst + doff,         A + (size_t)(row0 + row) * D_ + kb + c * 8);
        cp16(sdst + 16384 + doff, W + (size_t)(col0 + row) * D_ + kb + c * 8);
    }
    CP_COMMIT();
}

__device__ __forceinline__ void compute_chunk_h(uint32_t sbase,
                                                int wm, int wn, int lane,
                                                float acc[4][4][4])
{
    const uint32_t Ab = sbase;
    const uint32_t Bb = sbase + 16384;
    const int g  = lane >> 3;
    const int l8 = lane & 7;
    const int kh = (lane >> 3) & 1;   // B: k-half
    const int no = lane >> 4;         // B: n-octet
#pragma unroll
    for (int ks = 0; ks < 4; ks++) {
        uint32_t afr[4][4], bp[2][4];
#pragma unroll
        for (int mb = 0; mb < 4; mb++) {
            const int r = wm * 64 + mb * 16 + ((g & 1) << 3) + l8;
            const int u = 2 * ks + (g >> 1);
            ldsm_x4(afr[mb], Ab + r * 128 + ((u ^ (r & 7)) * 16));
        }
#pragma unroll
        for (int p = 0; p < 2; p++) {
            const int r = wn * 16 + p * 64 + (no << 3) + l8;
            const int u = 2 * ks + kh;
            ldsm_x4(bp[p], Bb + r * 128 + ((u ^ (r & 7)) * 16));
        }
#pragma unroll
        for (int mb = 0; mb < 4; mb++) {
#pragma unroll
            for (int p = 0; p < 2; p++) {
                mma_f16(acc[mb][2 * p],     afr[mb], &bp[p][0]);
                mma_f16(acc[mb][2 * p + 1], afr[mb], &bp[p][2]);
            }
        }
    }
}

// FUSED=1: z=0 -> fp16 rope'd+scaled Q; z=1 -> fp16 rope'd K; z=2 -> fp16 V^T.
// FUSED=0: fp32 C with bias (output projection).
template <int FUSED>
__global__ __launch_bounds__(256, 2)
void gemm_f16(const __half* __restrict__ A,
              const __half* __restrict__ W0, const __half* __restrict__ W1,
              const __half* __restrict__ W2,
              const float* __restrict__ b0, const float* __restrict__ b1,
              const float* __restrict__ b2,
              float* __restrict__ C0,
              __half* __restrict__ CQ, __half* __restrict__ CK,
              __half* __restrict__ CV)
{
    extern __shared__ char dsm[];
    const uint32_t s_u32 = smem_u32(dsm);

    const int z = FUSED ? blockIdx.z : 0;
    const __half* W    = (z == 0) ? W0 : (z == 1) ? W1 : W2;
    const float*  bias = (z == 0) ? b0 : (z == 1) ? b1 : b2;

    const int tid  = threadIdx.x;
    const int wid  = tid >> 5;
    const int lane = tid & 31;
    const int wm   = wid >> 2;
    const int wn   = wid & 3;
    const int lq   = lane >> 2;
    const int lr   = lane & 3;
    const int row0 = blockIdx.y << 7;
    const int col0 = blockIdx.x << 7;

    float acc[4][4][4];
#pragma unroll
    for (int i = 0; i < 4; i++)
#pragma unroll
        for (int j = 0; j < 4; j++)
#pragma unroll
            for (int r = 0; r < 4; r++) acc[i][j][r] = 0.f;

    const int NCH = D_ / 64;   // 32

    issue_chunk_h(s_u32,           A, W, row0, col0, 0,  tid);
    issue_chunk_h(s_u32 + HSTG_BY, A, W, row0, col0, 64, tid);

    for (int ch = 0; ch < NCH; ch++) {
        if (ch < NCH - 1) { CP_WAIT(1); } else { CP_WAIT(0); }
        __syncthreads();
        if (ch + 2 < NCH)
            issue_chunk_h(s_u32 + ((ch + 2) % 3) * HSTG_BY, A, W, row0, col0,
                          (ch + 2) * 64, tid);
        compute_chunk_h(s_u32 + (ch % 3) * HSTG_BY, wm, wn, lane, acc);
    }

    if (!FUSED) {
#pragma unroll
        for (int mb = 0; mb < 4; mb++) {
#pragma unroll
            for (int nb = 0; nb < 4; nb++) {
                const int col = col0 + wn * 16 + (nb & 1) * 8 + (nb >> 1) * 64 + lr * 2;
                const float2 bv = *(const float2*)(bias + col);
                const int r0 = row0 + wm * 64 + mb * 16 + lq;
                float2 o0, o1;
                o0.x = acc[mb][nb][0] + bv.x;
                o0.y = acc[mb][nb][1] + bv.y;
                o1.x = acc[mb][nb][2] + bv.x;
                o1.y = acc[mb][nb][3] + bv.y;
                *(float2*)(C0 + (size_t)r0 * D_ + col)       = o0;
                *(float2*)(C0 + (size_t)(r0 + 8) * D_ + col) = o1;
            }
        }
    } else if (z == 2) {
        const int bidx = row0 >> 11;
        const size_t vbase = ((size_t)bidx * 16 + blockIdx.x) * ((size_t)DH_ * S_);
#pragma unroll
        for (int mb = 0; mb < 4; mb++) {
#pragma unroll
            for (int nb = 0; nb < 4; nb++) {
                const int col = wn * 16 + (nb & 1) * 8 + (nb >> 1) * 64 + lr * 2;
                const float2 bv = *(const float2*)(bias + col0 + col);
                const int r0 = row0 + wm * 64 + mb * 16 + lq;
                const int s0 = r0 & (S_ - 1);
                CV[vbase + (size_t)(col    ) * S_ + s0]     = __float2half_rn(acc[mb][nb][0] + bv.x);
                CV[vbase + (size_t)(col + 1) * S_ + s0]     = __float2half_rn(acc[mb][nb][1] + bv.y);
                CV[vbase + (size_t)(col    ) * S_ + s0 + 8] = __float2half_rn(acc[mb][nb][2] + bv.x);
                CV[vbase + (size_t)(col + 1) * S_ + s0 + 8] = __float2half_rn(acc[mb][nb][3] + bv.y);
            }
        }
    } else {
        const float qs = (z == 0) ? 0.08838834764831845f : 1.0f;
        __half* Ch = (z == 0) ? CQ : CK;
        const float cexp = 13.287712379549449f / 64.f;
#pragma unroll
        for (int nbp = 0; nbp < 2; nbp++) {
            const int dcol = wn * 16 + nbp * 8 + 2 * lr;
            const float inv0 = exp2f(-(float)dcol * cexp);
            const float inv1 = exp2f(-(float)(dcol + 1) * cexp);
            const float2 bv  = *(const float2*)(bias + col0 + dcol);
            const float2 bv2 = *(const float2*)(bias + col0 + dcol + 64);
#pragma unroll
            for (int mb = 0; mb < 4; mb++) {
#pragma unroll
                for (int hf = 0; hf < 2; hf++) {
                    const int r = row0 + wm * 64 + mb * 16 + lq + hf * 8;
                    const float s = (float)(r & (S_ - 1));
                    float sn0, cs0, sn1, cs1;
                    sincosf(s * inv0, &sn0, &cs0);
                    sincosf(s * inv1, &sn1, &cs1);
                    const float v0 = acc[mb][nbp    ][hf * 2 + 0] + bv.x;
                    const float v1 = acc[mb][nbp    ][hf * 2 + 1] + bv.y;
                    const float p0 = acc[mb][nbp + 2][hf * 2 + 0] + bv2.x;
                    const float p1 = acc[mb][nbp + 2][hf * 2 + 1] + bv2.y;
                    *(__half2*)(Ch + (size_t)r * D_ + col0 + dcol) =
                        __floats2half2_rn((v0 * cs0 - p0 * sn0) * qs,
                                          (v1 * cs1 - p1 * sn1) * qs);
                    *(__half2*)(Ch + (size_t)r * D_ + col0 + dcol + 64) =
                        __floats2half2_rn((p0 * cs0 + v0 * sn0) * qs,
                                          (p1 * cs1 + v1 * sn1) * qs);
                }
            }
        }
    }
}

// ---------------- Flash attention (fp16 mma, pair-barrier softmax) ---------
// Bq = Bk = 64, Dh = 128, 256 threads = 8 warps: (wm 0..3) x (wn 0..1).
#define FQH_ST 136
#define FKH_ST 136
#define FVH_ST 72
#define FPS_ST 72
#define Q_BY   (64 * FQH_ST * 2)
#define K_BY   (64 * FKH_ST * 2)
#define V_BY   (128 * FVH_ST * 2)
#define KV_BY  (K_BY + V_BY)
#define PS_BY  (64 * FPS_ST * 2)
#define RED_BY ((128 + 128 + 64 + 64) * 4)
#define FLASH_BYTES (Q_BY + 2 * KV_BY + PS_BY + RED_BY)

__global__ __launch_bounds__(256, 2)
void flash_h(const __half* __restrict__ qh, const __half* __restrict__ kh,
             const __half* __restrict__ vh, __half* __restrict__ o)
{
    extern __shared__ char fsm[];
    const uint32_t Qs  = smem_u32(fsm);
    const uint32_t KV0 = Qs + Q_BY;
    const uint32_t Psm = KV0 + 2 * KV_BY;
    float* redmax = (float*)(fsm + Q_BY + 2 * KV_BY + PS_BY);  // [2][64]
    float* redsum = redmax + 128;                               // [2][64]
    float* row_m  = redsum + 128;                               // [64]
    float* row_l  = row_m + 64;                                 // [64]
    __half* Ps    = (__half*)(fsm + Q_BY + 2 * KV_BY);

    const int tid  = threadIdx.x;
    const int wid  = tid >> 5;
    const int lane = tid & 31;
    const int lq   = lane >> 2;
    const int lr   = lane & 3;
    const int g    = lane >> 3;
    const int l8   = lane & 7;
    const int kh2  = (lane >> 3) & 1;
    const int no   = lane >> 4;
    const int wm   = wid & 3;     // 0..3
    const int wn   = wid >> 2;    // 0..1
    const int q0   = blockIdx.x * 64;
    const int bh   = blockIdx.y;
    const int b    = bh >> 4, h = bh & 15;
    const size_t head  = (size_t)b * S_ * D_ + (size_t)h * DH_;
    const size_t vhead = (size_t)bh * ((size_t)DH_ * S_);
    const int NT = S_ / 64;
    const int r0 = wm * 16 + lq;

    // ---- issue Q, then K/V stage 0
#pragma unroll
    for (int i = 0; i < 4; i++) {
        int f = tid + i * 256;
        int r = f >> 4, c = f & 15;
        cp16(Qs + r * (FQH_ST * 2) + c * 16,
             qh + head + (size_t)(q0 + r) * D_ + c * 8);
    }
    CP_COMMIT();
#pragma unroll
    for (int i = 0; i < 4; i++) {
        int f = tid + i * 256;
        int r = f >> 4, c = f & 15;
        cp16(KV0 + r * (FKH_ST * 2) + c * 16,
             kh + head + (size_t)r * D_ + c * 8);
    }
#pragma unroll
    for (int i = 0; i < 4; i++) {
        int f = tid + i * 256;
        int r = f >> 3, c = f & 7;
        cp16(KV0 + K_BY + r * (FVH_ST * 2) + c * 16,
             vh + vhead + (size_t)r * S_ + c * 8);
    }
    CP_COMMIT();

    if (tid < 64) { row_m[tid] = -1e30f; row_l[tid] = 0.f; }

    float oacc[8][4];
#pragma unroll
    for (int i = 0; i < 8; i++)
#pragma unroll
        for (int j = 0; j < 4; j++) oacc[i][j] = 0.f;

    CP_WAIT(0);
    __syncthreads();

    uint32_t qfr[8][4];
#pragma unroll
    for (int ks = 0; ks < 8; ks++) {
        const int r = wm * 16 + ((g & 1) << 3) + l8;
        ldsm_x4(qfr[ks], Qs + (r * FQH_ST + ks * 16 + (g >> 1) * 8) * 2);
    }

    for (int kt = 0; kt < NT; kt++) {
        const uint32_t KVc = KV0 + (kt & 1) * KV_BY;
        if (kt > 0) {
            CP_WAIT(0);
            __syncthreads();
        }
        // ---- issue prefetch for kt+1 (after the barrier: KVc reads all done)
        if (kt + 1 < NT) {
            const uint32_t KVn = KV0 + ((kt + 1) & 1) * KV_BY;
            const int kg = (kt + 1) * 64;
#pragma unroll
            for (int i = 0; i < 4; i++) {
                int f = tid + i * 256;
                int r = f >> 4, c = f & 15;
                cp16(KVn + r * (FKH_ST * 2) + c * 16,
                     kh + head + (size_t)(kg + r) * D_ + c * 8);
            }
#pragma unroll
            for (int i = 0; i < 4; i++) {
                int f = tid + i * 256;
                int r = f >> 3, c = f & 7;
                cp16(KVn + K_BY + r * (FVH_ST * 2) + c * 16,
                     vh + vhead + (size_t)r * S_ + kg + c * 8);
            }
            CP_COMMIT();
        }

        // ---- S = Q K^T (warp tile 16x32)
        float sacc[4][4];
#pragma unroll
        for (int i = 0; i < 4; i++)
#pragma unroll
            for (int j = 0; j < 4; j++) sacc[i][j] = 0.f;

#pragma unroll
        for (int ks = 0; ks < 8; ks++) {
            uint32_t bp[2][4];
#pragma unroll
            for (int p = 0; p < 2; p++) {
                const int n = wn * 32 + p * 16 + (no << 3) + l8;
                ldsm_x4(bp[p], KVc + (n * FKH_ST + ks * 16 + kh2 * 8) * 2);
            }
#pragma unroll
            for (int p = 0; p < 2; p++) {
                mma_f16(sacc[2 * p],     qfr[ks], &bp[p][0]);
                mma_f16(sacc[2 * p + 1], qfr[ks], &bp[p][2]);
            }
        }

        // ---- phase A: per-warp row max, pair-barrier exchange
        float m0 = -1e30f, m1 = -1e30f;
#pragma unroll
        for (int nb = 0; nb < 4; nb++) {
            m0 = fmaxf(m0, fmaxf(sacc[nb][0], sacc[nb][1]));
            m1 = fmaxf(m1, fmaxf(sacc[nb][2], sacc[nb][3]));
        }
        m0 = fmaxf(m0, __shfl_xor_sync(0xffffffffu, m0, 1));
        m0 = fmaxf(m0, __shfl_xor_sync(0xffffffffu, m0, 2));
        m1 = fmaxf(m1, __shfl_xor_sync(0xffffffffu, m1, 1));
        m1 = fmaxf(m1, __shfl_xor_sync(0xffffffffu, m1, 2));
        if (lr == 0) {
            redmax[wn * 64 + r0]     = m0;
            redmax[wn * 64 + r0 + 8] = m1;
        }
        BARPAIR(wm);

        // ---- phase B: combine, exp in registers, write fp16 P
        const float mo0 = row_m[r0], mo1 = row_m[r0 + 8];
        const float mn0 = fmaxf(mo0, fmaxf(redmax[r0],     redmax[64 + r0]));
        const float mn1 = fmaxf(mo1, fmaxf(redmax[r0 + 8], redmax[64 + r0 + 8]));
        const float al0 = __expf(mo0 - mn0);
        const float al1 = __expf(mo1 - mn1);
        float s0 = 0.f, s1 = 0.f;
#pragma unroll
        for (int nb = 0; nb < 4; nb++) {
            const int col = wn * 32 + nb * 8 + 2 * lr;
            float p0 = __expf(sacc[nb][0] - mn0);
            float p1 = __expf(sacc[nb][1] - mn0);
            float p2 = __expf(sacc[nb][2] - mn1);
            float p3 = __expf(sacc[nb][3] - mn1);
            s0 += p0 + p1;
            s1 += p2 + p3;
            *(__half2*)(Ps + (r0    ) * FPS_ST + col) = __floats2half2_rn(p0, p1);
            *(__half2*)(Ps + (r0 + 8) * FPS_ST + col) = __floats2half2_rn(p2, p3);
        }
        s0 += __shfl_xor_sync(0xffffffffu, s0, 1);
        s0 += __shfl_xor_sync(0xffffffffu, s0, 2);
        s1 += __shfl_xor_sync(0xffffffffu, s1, 1);
        s1 += __shfl_xor_sync(0xffffffffu, s1, 2);
        if (lr == 0) {
            redsum[wn * 64 + r0]     = s0;
            redsum[wn * 64 + r0 + 8] = s1;
        }
#pragma unroll
        for (int nb = 0; nb < 8; nb++) {
            oacc[nb][0] *= al0; oacc[nb][1] *= al0;
            oacc[nb][2] *= al1; oacc[nb][3] *= al1;
        }
        BARPAIR(wm);

        // ---- phase C: designated thread updates running (m, l)
        if (wn == 0 && lr == 0) {
            row_l[r0]     = row_l[r0]     * al0 + redsum[r0]     + redsum[64 + r0];
            row_m[r0]     = mn0;
            row_l[r0 + 8] = row_l[r0 + 8] * al1 + redsum[r0 + 8] + redsum[64 + r0 + 8];
            row_m[r0 + 8] = mn1;
        }

        // ---- O += P V (warp tile 16x64)
#pragma unroll
        for (int ks = 0; ks < 4; ks++) {
            uint32_t a[4], bp[4][4];
            const int ar = wm * 16 + ((g & 1) << 3) + l8;
            ldsm_x4(a, Psm + (ar * FPS_ST + ks * 16 + (g >> 1) * 8) * 2);
#pragma unroll
            for (int p = 0; p < 4; p++) {
                const int n = wn * 64 + p * 16 + (no << 3) + l8;
                ldsm_x4(bp[p], KVc + K_BY + (n * FVH_ST + ks * 16 + kh2 * 8) * 2);
            }
#pragma unroll
            for (int p = 0; p < 4; p++) {
                mma_f16(oacc[2 * p],     a, &bp[p][0]);
                mma_f16(oacc[2 * p + 1], a, &bp[p][2]);
            }
        }
        // no trailing CTA sync: next-iteration top sync precedes KV overwrite,
        // and phase-A/B pair barriers precede the next Ps write.
    }

    BARPAIR(wm);   // row_l final values visible to both wn warps

    // ---- epilogue: normalize, write fp16 att
    const float il0 = 1.f / row_l[r0];
    const float il1 = 1.f / row_l[r0 + 8];
#pragma unroll
    for (int nb = 0; nb < 8; nb++) {
        const int col = wn * 64 + nb * 8 + 2 * lr;
        const int r   = q0 + r0;
        *(__half2*)(o + head + (size_t)r * D_ + col) =
            __floats2half2_rn(oacc[nb][0] * il0, oacc[nb][1] * il0);
        *(__half2*)(o + head + (size_t)(r + 8) * D_ + col) =
            __floats2half2_rn(oacc[nb][2] * il1, oacc[nb][3] * il1);
    }
}

// ---------------- launch ---------------------------------------------------
extern "C" void kernel_launch(void* const* d_in, const int* in_sizes, int n_in,
                              void* d_out, int out_size)
{
    const float* x   = (const float*)d_in[0];
    const float* q_w = (const float*)d_in[1];
    const float* k_w = (const float*)d_in[2];
    const float* v_w = (const float*)d_in[3];
    const float* q_b = (const float*)d_in[4];
    const float* k_b = (const float*)d_in[5];
    const float* v_b = (const float*)d_in[6];
    const float* o_w = (const float*)d_in[7];
    const float* o_b = (const float*)d_in[8];
    float* out = (float*)d_out;

    __half *qhp, *khp, *vhp, *xh, *wqh, *wkh, *wvh, *woh, *ath;
    cudaGetSymbolAddress((void**)&qhp, g_qh);
    cudaGetSymbolAddress((void**)&khp, g_kh);
    cudaGetSymbolAddress((void**)&vhp, g_vh);
    cudaGetSymbolAddress((void**)&xh,  g_xh);
    cudaGetSymbolAddress((void**)&wqh, g_wqh);
    cudaGetSymbolAddress((void**)&wkh, g_wkh);
    cudaGetSymbolAddress((void**)&wvh, g_wvh);
    cudaGetSymbolAddress((void**)&woh, g_woh);
    cudaGetSymbolAddress((void**)&ath, g_atth);

    cudaFuncSetAttribute(flash_h,
                         cudaFuncAttributeMaxDynamicSharedMemorySize, FLASH_BYTES);
    cudaFuncSetAttribute(gemm_f16<1>,
                         cudaFuncAttributeMaxDynamicSharedMemorySize, GEMM_SMEM);
    cudaFuncSetAttribute(gemm_f16<0>,
                         cudaFuncAttributeMaxDynamicSharedMemorySize, GEMM_SMEM);

    const int total4 = XN4 + 4 * WN4;
    conv_all<<<total4 / 256, 256>>>(
        (const float4*)x, (const float4*)q_w, (const float4*)k_w,
        (const float4*)v_w, (const float4*)o_w,
        (H4*)xh, (H4*)wqh, (H4*)wkh, (H4*)wvh, (H4*)woh);

    gemm_f16<1><<<dim3(D_ / 128, M_ / 128, 3), 256, GEMM_SMEM>>>(
        xh, wqh, wkh, wvh, q_b, k_b, v_b,
        (float*)nullptr, qhp, khp, vhp);

    flash_h<<<dim3(S_ / 64, B_ * H_), 256, FLASH_BYTES>>>(qhp, khp, vhp, ath);

    gemm_f16<0><<<dim3(D_ / 128, M_ / 128, 1), 256, GEMM_SMEM>>>(
        ath, woh, woh, woh, o_b, o_b, o_b,
        out, (__half*)nullptr, (__half*)nullptr, (__half*)nullptr);
}